// round 2
// baseline (speedup 1.0000x reference)
#include <cuda_runtime.h>
#include <cstdint>
#include <cmath>

// Problem constants
constexpr int Dm   = 1024;   // d_model
constexpr int Lb   = 1024;   // block length (SEQ / SPLIT)
constexpr int NSP  = 4;      // SPLIT
constexpr int NB   = 4;      // batch
constexpr int NH   = 16;     // heads
constexpr int DK   = 64;     // head dim
constexpr int NZ   = NB * NSP;  // 16 independent (b,s) blocks

// Scratch (allocation-free rule: __device__ globals)
__device__ float g_Q[(size_t)NZ * Lb * Dm];
__device__ float g_K[(size_t)NZ * Lb * Dm];
__device__ float g_V[(size_t)NZ * Lb * Dm];
__device__ float g_O[(size_t)NZ * Lb * Dm];

__device__ __forceinline__ uint32_t f2tf(float f) {
    uint32_t u;
    asm("cvt.rna.tf32.f32 %0, %1;" : "=r"(u) : "f"(f));
    return u;
}

__device__ __forceinline__ void mma_tf32(float c[4], const uint32_t a[4],
                                         uint32_t b0, uint32_t b1) {
    asm volatile(
        "mma.sync.aligned.m16n8k8.row.col.f32.tf32.tf32.f32 "
        "{%0,%1,%2,%3}, {%4,%5,%6,%7}, {%8,%9}, {%0,%1,%2,%3};\n"
        : "+f"(c[0]), "+f"(c[1]), "+f"(c[2]), "+f"(c[3])
        : "r"(a[0]), "r"(a[1]), "r"(a[2]), "r"(a[3]), "r"(b0), "r"(b1));
}

// ============================================================================
// GEMM: C[z] = X[z] @ W[z%NSP] + bias[z%NSP]
//   X viewed as NZ stacked [Lb, Dm] blocks (x layout [B,SEQ,D]: block (b,s)
//   starts at row (b*NSP+s)*Lb = z*Lb). Tile 128x128x32, 8 warps, tf32 mma.
// ============================================================================
#define BM 128
#define BN 128
#define BKg 32

__global__ __launch_bounds__(256) void gemm_tf32(const float* __restrict__ X,
                                                 const float* __restrict__ W,
                                                 const float* __restrict__ bias,
                                                 float* __restrict__ C) {
    __shared__ uint32_t As[BM][BKg + 4];   // row stride 36 ≡ 4 mod 32 → frag reads conflict-free
    __shared__ uint32_t Bs[BKg][BN + 4];   // row stride 132 ≡ 4 mod 32

    const int z = blockIdx.z;
    const float* Xb = X + (size_t)z * Lb * Dm;
    const float* Wb = W + (size_t)(z % NSP) * Dm * Dm;
    const float* bb = bias + (size_t)(z % NSP) * Dm;
    float* Cb = C + (size_t)z * Lb * Dm;

    const int m0 = blockIdx.y * BM, n0 = blockIdx.x * BN;
    const int tid = threadIdx.x;
    const int wid = tid >> 5, lane = tid & 31;
    const int gid = lane >> 2, t4 = lane & 3;
    const int wm = (wid & 3) * 32;     // 4 warps along M (32 rows each)
    const int wn = (wid >> 2) * 64;    // 2 warps along N (64 cols each)

    float acc[2][8][4];
#pragma unroll
    for (int i = 0; i < 2; i++)
#pragma unroll
        for (int j = 0; j < 8; j++)
#pragma unroll
            for (int k = 0; k < 4; k++) acc[i][j][k] = 0.f;

    for (int k0 = 0; k0 < Dm; k0 += BKg) {
        // Load A tile 128x32 (4 passes of 32 rows)
#pragma unroll
        for (int i = 0; i < 4; i++) {
            int r = i * 32 + (tid >> 3);
            int c = (tid & 7) * 4;
            float4 v = *(const float4*)(Xb + (size_t)(m0 + r) * Dm + k0 + c);
            As[r][c + 0] = f2tf(v.x); As[r][c + 1] = f2tf(v.y);
            As[r][c + 2] = f2tf(v.z); As[r][c + 3] = f2tf(v.w);
        }
        // Load B tile 32x128 (4 passes of 8 rows)
#pragma unroll
        for (int i = 0; i < 4; i++) {
            int r = i * 8 + (tid >> 5);
            int c = (tid & 31) * 4;
            float4 v = *(const float4*)(Wb + (size_t)(k0 + r) * Dm + n0 + c);
            Bs[r][c + 0] = f2tf(v.x); Bs[r][c + 1] = f2tf(v.y);
            Bs[r][c + 2] = f2tf(v.z); Bs[r][c + 3] = f2tf(v.w);
        }
        __syncthreads();

#pragma unroll
        for (int kk = 0; kk < BKg; kk += 8) {
            uint32_t a[2][4];
#pragma unroll
            for (int mt = 0; mt < 2; mt++) {
                int rb = wm + mt * 16;
                a[mt][0] = As[rb + gid][kk + t4];
                a[mt][1] = As[rb + 8 + gid][kk + t4];
                a[mt][2] = As[rb + gid][kk + t4 + 4];
                a[mt][3] = As[rb + 8 + gid][kk + t4 + 4];
            }
#pragma unroll
            for (int nt = 0; nt < 8; nt++) {
                int cb = wn + nt * 8 + gid;
                uint32_t b0 = Bs[kk + t4][cb];
                uint32_t b1 = Bs[kk + 4 + t4][cb];
#pragma unroll
                for (int mt = 0; mt < 2; mt++) mma_tf32(acc[mt][nt], a[mt], b0, b1);
            }
        }
        __syncthreads();
    }

    // Epilogue: + bias, write fp32
#pragma unroll
    for (int mt = 0; mt < 2; mt++) {
        int r0 = m0 + wm + mt * 16 + gid;
#pragma unroll
        for (int nt = 0; nt < 8; nt++) {
            int c0 = n0 + wn + nt * 8 + 2 * t4;
            float bv0 = bb[c0], bv1 = bb[c0 + 1];
            Cb[(size_t)r0 * Dm + c0]       = acc[mt][nt][0] + bv0;
            Cb[(size_t)r0 * Dm + c0 + 1]   = acc[mt][nt][1] + bv1;
            Cb[(size_t)(r0 + 8) * Dm + c0]     = acc[mt][nt][2] + bv0;
            Cb[(size_t)(r0 + 8) * Dm + c0 + 1] = acc[mt][nt][3] + bv1;
        }
    }
}

// ============================================================================
// Flash attention per (z, h): q,k,v [Lb, DK]; causal within block.
// CTA: 64 query rows (grid.x = Lb/64 = 16), 4 warps × 16 rows.
// Key tiles of 64, only j <= qt (causal skip).
// SMEM pads: Ks/Ps stride 68 (≡4 mod 32, conflict-free frag reads),
//            Vs stride 72 (≡8 mod 32, conflict-free B-frag reads).
// ============================================================================
constexpr int KS_STR = 68;
constexpr int VS_STR = 72;
constexpr int ATTN_SMEM = 64 * (KS_STR + VS_STR + KS_STR) * 4;  // 53248 B

__global__ __launch_bounds__(128) void attn_kernel(const float* __restrict__ Q,
                                                   const float* __restrict__ K,
                                                   const float* __restrict__ V,
                                                   float* __restrict__ O) {
    extern __shared__ uint32_t sm[];
    uint32_t (*Ks)[KS_STR] = (uint32_t(*)[KS_STR])sm;
    uint32_t (*Vs)[VS_STR] = (uint32_t(*)[VS_STR])(sm + 64 * KS_STR);
    uint32_t (*Ps)[KS_STR] = (uint32_t(*)[KS_STR])(sm + 64 * KS_STR + 64 * VS_STR);

    const int qt = blockIdx.x;      // query tile (0..15)
    const int h  = blockIdx.y;
    const int z  = blockIdx.z;      // b*NSP+s
    const size_t base = (size_t)z * Lb * Dm + h * DK;

    const int tid = threadIdx.x;
    const int wid = tid >> 5, lane = tid & 31;
    const int gid = lane >> 2, t4 = lane & 3;
    const int wrow = wid * 16;
    const float scale = 0.125f;     // 1/sqrt(DK)

    // Stage Q tile (scaled, tf32) into Ps, build A-fragments in registers
#pragma unroll
    for (int i = 0; i < 8; i++) {
        int r = i * 8 + (tid >> 4);
        int c = (tid & 15) * 4;
        float4 v = *(const float4*)(Q + base + (size_t)(qt * 64 + r) * Dm + c);
        Ps[r][c + 0] = f2tf(v.x * scale); Ps[r][c + 1] = f2tf(v.y * scale);
        Ps[r][c + 2] = f2tf(v.z * scale); Ps[r][c + 3] = f2tf(v.w * scale);
    }
    __syncthreads();

    uint32_t qa[8][4];
#pragma unroll
    for (int ks = 0; ks < 8; ks++) {
        qa[ks][0] = Ps[wrow + gid][ks * 8 + t4];
        qa[ks][1] = Ps[wrow + 8 + gid][ks * 8 + t4];
        qa[ks][2] = Ps[wrow + gid][ks * 8 + t4 + 4];
        qa[ks][3] = Ps[wrow + 8 + gid][ks * 8 + t4 + 4];
    }

    float acc[8][4];
#pragma unroll
    for (int nt = 0; nt < 8; nt++)
#pragma unroll
        for (int k = 0; k < 4; k++) acc[nt][k] = 0.f;
    float mrow0 = -INFINITY, mrow1 = -INFINITY;
    float lrow0 = 0.f, lrow1 = 0.f;

    for (int j = 0; j <= qt; j++) {
        __syncthreads();   // everyone done with Ks/Vs (and initial Ps reads)
        // Load K,V tile j (64x64 each)
#pragma unroll
        for (int i = 0; i < 8; i++) {
            int r = i * 8 + (tid >> 4);
            int c = (tid & 15) * 4;
            size_t off = base + (size_t)(j * 64 + r) * Dm + c;
            float4 kv = *(const float4*)(K + off);
            float4 vv = *(const float4*)(V + off);
            Ks[r][c + 0] = f2tf(kv.x); Ks[r][c + 1] = f2tf(kv.y);
            Ks[r][c + 2] = f2tf(kv.z); Ks[r][c + 3] = f2tf(kv.w);
            Vs[r][c + 0] = f2tf(vv.x); Vs[r][c + 1] = f2tf(vv.y);
            Vs[r][c + 2] = f2tf(vv.z); Vs[r][c + 3] = f2tf(vv.w);
        }
        __syncthreads();

        // S = (Q*scale) @ K^T   [16 rows/warp x 64 keys]
        float s[8][4];
#pragma unroll
        for (int nt = 0; nt < 8; nt++)
#pragma unroll
            for (int k = 0; k < 4; k++) s[nt][k] = 0.f;
#pragma unroll
        for (int ks = 0; ks < 8; ks++) {
#pragma unroll
            for (int nt = 0; nt < 8; nt++) {
                uint32_t b0 = Ks[nt * 8 + gid][ks * 8 + t4];
                uint32_t b1 = Ks[nt * 8 + gid][ks * 8 + t4 + 4];
                mma_tf32(s[nt], qa[ks], b0, b1);
            }
        }

        // Causal mask (only diagonal tile)
        if (j == qt) {
            int r0 = wrow + gid, r1 = wrow + gid + 8;
#pragma unroll
            for (int nt = 0; nt < 8; nt++) {
                int c0 = nt * 8 + 2 * t4;
                if (c0 > r0)     s[nt][0] = -1e30f;
                if (c0 + 1 > r0) s[nt][1] = -1e30f;
                if (c0 > r1)     s[nt][2] = -1e30f;
                if (c0 + 1 > r1) s[nt][3] = -1e30f;
            }
        }

        // Online softmax
        float mx0 = -INFINITY, mx1 = -INFINITY;
#pragma unroll
        for (int nt = 0; nt < 8; nt++) {
            mx0 = fmaxf(mx0, fmaxf(s[nt][0], s[nt][1]));
            mx1 = fmaxf(mx1, fmaxf(s[nt][2], s[nt][3]));
        }
        mx0 = fmaxf(mx0, __shfl_xor_sync(0xffffffffu, mx0, 1));
        mx0 = fmaxf(mx0, __shfl_xor_sync(0xffffffffu, mx0, 2));
        mx1 = fmaxf(mx1, __shfl_xor_sync(0xffffffffu, mx1, 1));
        mx1 = fmaxf(mx1, __shfl_xor_sync(0xffffffffu, mx1, 2));

        float mn0 = fmaxf(mrow0, mx0), mn1 = fmaxf(mrow1, mx1);
        float cor0 = __expf(mrow0 - mn0), cor1 = __expf(mrow1 - mn1);
        mrow0 = mn0; mrow1 = mn1;

        float ls0 = 0.f, ls1 = 0.f;
#pragma unroll
        for (int nt = 0; nt < 8; nt++) {
            s[nt][0] = __expf(s[nt][0] - mn0);
            s[nt][1] = __expf(s[nt][1] - mn0);
            s[nt][2] = __expf(s[nt][2] - mn1);
            s[nt][3] = __expf(s[nt][3] - mn1);
            ls0 += s[nt][0] + s[nt][1];
            ls1 += s[nt][2] + s[nt][3];
        }
        ls0 += __shfl_xor_sync(0xffffffffu, ls0, 1);
        ls0 += __shfl_xor_sync(0xffffffffu, ls0, 2);
        ls1 += __shfl_xor_sync(0xffffffffu, ls1, 1);
        ls1 += __shfl_xor_sync(0xffffffffu, ls1, 2);
        lrow0 = lrow0 * cor0 + ls0;
        lrow1 = lrow1 * cor1 + ls1;

#pragma unroll
        for (int nt = 0; nt < 8; nt++) {
            acc[nt][0] *= cor0; acc[nt][1] *= cor0;
            acc[nt][2] *= cor1; acc[nt][3] *= cor1;
        }

        // Stage P (tf32) — warp-private rows, warp-sync is enough
#pragma unroll
        for (int nt = 0; nt < 8; nt++) {
            int c0 = nt * 8 + 2 * t4;
            Ps[wrow + gid][c0]         = f2tf(s[nt][0]);
            Ps[wrow + gid][c0 + 1]     = f2tf(s[nt][1]);
            Ps[wrow + 8 + gid][c0]     = f2tf(s[nt][2]);
            Ps[wrow + 8 + gid][c0 + 1] = f2tf(s[nt][3]);
        }
        __syncwarp();

        // O += P @ V
#pragma unroll
        for (int ks = 0; ks < 8; ks++) {
            uint32_t pa[4];
            pa[0] = Ps[wrow + gid][ks * 8 + t4];
            pa[1] = Ps[wrow + 8 + gid][ks * 8 + t4];
            pa[2] = Ps[wrow + gid][ks * 8 + t4 + 4];
            pa[3] = Ps[wrow + 8 + gid][ks * 8 + t4 + 4];
#pragma unroll
            for (int nt = 0; nt < 8; nt++) {
                uint32_t vb0 = Vs[ks * 8 + t4][nt * 8 + gid];
                uint32_t vb1 = Vs[ks * 8 + 4 + t4][nt * 8 + gid];
                mma_tf32(acc[nt], pa, vb0, vb1);
            }
        }
    }

    // Finalize: divide by row sums, write O
    float inv0 = 1.f / lrow0, inv1 = 1.f / lrow1;
    int r0 = qt * 64 + wrow + gid;
#pragma unroll
    for (int nt = 0; nt < 8; nt++) {
        int c0 = nt * 8 + 2 * t4;
        O[base + (size_t)r0 * Dm + c0]           = acc[nt][0] * inv0;
        O[base + (size_t)r0 * Dm + c0 + 1]       = acc[nt][1] * inv0;
        O[base + (size_t)(r0 + 8) * Dm + c0]     = acc[nt][2] * inv1;
        O[base + (size_t)(r0 + 8) * Dm + c0 + 1] = acc[nt][3] * inv1;
    }
}

// ============================================================================
// Launch
// ============================================================================
extern "C" void kernel_launch(void* const* d_in, const int* in_sizes, int n_in,
                              void* d_out, int out_size) {
    const float* x  = (const float*)d_in[0];
    const float* Wq = (const float*)d_in[1];
    const float* Wk = (const float*)d_in[2];
    const float* Wv = (const float*)d_in[3];
    const float* Wo = (const float*)d_in[4];
    const float* bq = (const float*)d_in[5];
    const float* bk = (const float*)d_in[6];
    const float* bv = (const float*)d_in[7];
    const float* bo = (const float*)d_in[8];
    float* out = (float*)d_out;

    float *gq, *gk, *gv, *go;
    cudaGetSymbolAddress((void**)&gq, g_Q);
    cudaGetSymbolAddress((void**)&gk, g_K);
    cudaGetSymbolAddress((void**)&gv, g_V);
    cudaGetSymbolAddress((void**)&go, g_O);

    cudaFuncSetAttribute(attn_kernel, cudaFuncAttributeMaxDynamicSharedMemorySize,
                         ATTN_SMEM);

    dim3 gg(Dm / BN, Lb / BM, NZ);   // (8, 8, 16)
    dim3 gb(256);
    gemm_tf32<<<gg, gb>>>(x, Wq, bq, gq);
    gemm_tf32<<<gg, gb>>>(x, Wk, bk, gk);
    gemm_tf32<<<gg, gb>>>(x, Wv, bv, gv);
    attn_kernel<<<dim3(Lb / 64, NH, NZ), 128, ATTN_SMEM>>>(gq, gk, gv, go);
    gemm_tf32<<<gg, gb>>>(go, Wo, bo, out);
}

// round 4
// speedup vs baseline: 1.1160x; 1.1160x over previous
#include <cuda_runtime.h>
#include <cstdint>
#include <cmath>

// Problem constants
constexpr int Dm   = 1024;   // d_model
constexpr int Lb   = 1024;   // block length (SEQ / SPLIT)
constexpr int NSP  = 4;      // SPLIT
constexpr int NB   = 4;      // batch
constexpr int NH   = 16;     // heads
constexpr int DK   = 64;     // head dim
constexpr int NZ   = NB * NSP;  // 16 independent (b,s) blocks

// Scratch (allocation-free rule: __device__ globals)
__device__ float g_Q[(size_t)NZ * Lb * Dm];
__device__ float g_K[(size_t)NZ * Lb * Dm];
__device__ float g_V[(size_t)NZ * Lb * Dm];
__device__ float g_O[(size_t)NZ * Lb * Dm];

__device__ __forceinline__ uint32_t f2tf(float f) {
    uint32_t u;
    asm("cvt.rna.tf32.f32 %0, %1;" : "=r"(u) : "f"(f));
    return u;
}

__device__ __forceinline__ void mma_tf32(float c[4], const uint32_t a[4],
                                         uint32_t b0, uint32_t b1) {
    asm volatile(
        "mma.sync.aligned.m16n8k8.row.col.f32.tf32.tf32.f32 "
        "{%0,%1,%2,%3}, {%4,%5,%6,%7}, {%8,%9}, {%0,%1,%2,%3};\n"
        : "+f"(c[0]), "+f"(c[1]), "+f"(c[2]), "+f"(c[3])
        : "r"(a[0]), "r"(a[1]), "r"(a[2]), "r"(a[3]), "r"(b0), "r"(b1));
}

// ============================================================================
// GEMM: C[z] = X[z] @ W[z%NSP] + bias[z%NSP]
// Tile 128x128x32, 8 warps, tf32 mma.sync, REGISTER-PREFETCH PIPELINE:
//   LDG for chunk c+1 is issued before the chunk-c MMA loop and STS'd after
//   the trailing sync, so global latency overlaps tensor work.
// ============================================================================
#define BM 128
#define BN 128
#define BKg 32

__global__ __launch_bounds__(256) void gemm_tf32(const float* __restrict__ X,
                                                 const float* __restrict__ W,
                                                 const float* __restrict__ bias,
                                                 float* __restrict__ C) {
    __shared__ uint32_t As[BM][BKg + 4];   // row stride 36 ≡ 4 mod 32 → conflict-free
    __shared__ uint32_t Bs[BKg][BN + 4];   // row stride 132 ≡ 4 mod 32

    const int z = blockIdx.z;
    const float* Xb = X + (size_t)z * Lb * Dm;
    const float* Wb = W + (size_t)(z % NSP) * Dm * Dm;
    const float* bb = bias + (size_t)(z % NSP) * Dm;
    float* Cb = C + (size_t)z * Lb * Dm;

    const int m0 = blockIdx.y * BM, n0 = blockIdx.x * BN;
    const int tid = threadIdx.x;
    const int wid = tid >> 5, lane = tid & 31;
    const int gid = lane >> 2, t4 = lane & 3;
    const int wm = (wid & 3) * 32;     // 4 warps along M (32 rows each)
    const int wn = (wid >> 2) * 64;    // 2 warps along N (64 cols each)

    // Per-thread LDG addresses (fixed across chunks; advance by BKg / BKg*Dm)
    const int ar = tid >> 3, ac = (tid & 7) * 4;     // A: 32-row groups
    const int br = tid >> 5, bc = (tid & 31) * 4;    // B: 8-row groups
    const float* pA = Xb + (size_t)(m0 + ar) * Dm + ac;
    const float* pB = Wb + (size_t)br * Dm + n0 + bc;

    float4 aReg[4], bReg[4];
#pragma unroll
    for (int i = 0; i < 4; i++) {
        aReg[i] = *(const float4*)(pA + (size_t)(i * 32) * Dm);
        bReg[i] = *(const float4*)(pB + (size_t)(i * 8) * Dm);
    }

    float acc[2][8][4];
#pragma unroll
    for (int i = 0; i < 2; i++)
#pragma unroll
        for (int j = 0; j < 8; j++)
#pragma unroll
            for (int k = 0; k < 4; k++) acc[i][j][k] = 0.f;

    const int NCHUNK = Dm / BKg;   // 32
    for (int c = 0; c < NCHUNK; c++) {
        // Commit current registers to SMEM (tf32 conversion here, once/element)
#pragma unroll
        for (int i = 0; i < 4; i++) {
            As[ar + i * 32][ac + 0] = f2tf(aReg[i].x);
            As[ar + i * 32][ac + 1] = f2tf(aReg[i].y);
            As[ar + i * 32][ac + 2] = f2tf(aReg[i].z);
            As[ar + i * 32][ac + 3] = f2tf(aReg[i].w);
            Bs[br + i * 8][bc + 0] = f2tf(bReg[i].x);
            Bs[br + i * 8][bc + 1] = f2tf(bReg[i].y);
            Bs[br + i * 8][bc + 2] = f2tf(bReg[i].z);
            Bs[br + i * 8][bc + 3] = f2tf(bReg[i].w);
        }
        __syncthreads();

        // Prefetch next chunk (overlaps the MMA loop below)
        if (c + 1 < NCHUNK) {
            const float* nA = pA + (size_t)(c + 1) * BKg;
            const float* nB = pB + (size_t)(c + 1) * BKg * Dm;
#pragma unroll
            for (int i = 0; i < 4; i++) {
                aReg[i] = *(const float4*)(nA + (size_t)(i * 32) * Dm);
                bReg[i] = *(const float4*)(nB + (size_t)(i * 8) * Dm);
            }
        }

        // Compute chunk c
#pragma unroll
        for (int kk = 0; kk < BKg; kk += 8) {
            uint32_t a[2][4];
#pragma unroll
            for (int mt = 0; mt < 2; mt++) {
                int rb = wm + mt * 16;
                a[mt][0] = As[rb + gid][kk + t4];
                a[mt][1] = As[rb + 8 + gid][kk + t4];
                a[mt][2] = As[rb + gid][kk + t4 + 4];
                a[mt][3] = As[rb + 8 + gid][kk + t4 + 4];
            }
#pragma unroll
            for (int nt = 0; nt < 8; nt++) {
                int cb = wn + nt * 8 + gid;
                uint32_t b0 = Bs[kk + t4][cb];
                uint32_t b1 = Bs[kk + 4 + t4][cb];
#pragma unroll
                for (int mt = 0; mt < 2; mt++) mma_tf32(acc[mt][nt], a[mt], b0, b1);
            }
        }
        __syncthreads();
    }

    // Epilogue: + bias, write fp32
#pragma unroll
    for (int mt = 0; mt < 2; mt++) {
        int r0 = m0 + wm + mt * 16 + gid;
#pragma unroll
        for (int nt = 0; nt < 8; nt++) {
            int c0 = n0 + wn + nt * 8 + 2 * t4;
            float bv0 = bb[c0], bv1 = bb[c0 + 1];
            Cb[(size_t)r0 * Dm + c0]       = acc[mt][nt][0] + bv0;
            Cb[(size_t)r0 * Dm + c0 + 1]   = acc[mt][nt][1] + bv1;
            Cb[(size_t)(r0 + 8) * Dm + c0]     = acc[mt][nt][2] + bv0;
            Cb[(size_t)(r0 + 8) * Dm + c0 + 1] = acc[mt][nt][3] + bv1;
        }
    }
}

// ============================================================================
// Flash attention per (z, h) — unchanged from round 2 (327 us measured).
// ============================================================================
constexpr int KS_STR = 68;
constexpr int VS_STR = 72;
constexpr int ATTN_SMEM = 64 * (KS_STR + VS_STR + KS_STR) * 4;  // 53248 B

__global__ __launch_bounds__(128) void attn_kernel(const float* __restrict__ Q,
                                                   const float* __restrict__ K,
                                                   const float* __restrict__ V,
                                                   float* __restrict__ O) {
    extern __shared__ uint32_t sm[];
    uint32_t (*Ks)[KS_STR] = (uint32_t(*)[KS_STR])sm;
    uint32_t (*Vs)[VS_STR] = (uint32_t(*)[VS_STR])(sm + 64 * KS_STR);
    uint32_t (*Ps)[KS_STR] = (uint32_t(*)[KS_STR])(sm + 64 * KS_STR + 64 * VS_STR);

    const int qt = blockIdx.x;
    const int h  = blockIdx.y;
    const int z  = blockIdx.z;
    const size_t base = (size_t)z * Lb * Dm + h * DK;

    const int tid = threadIdx.x;
    const int wid = tid >> 5, lane = tid & 31;
    const int gid = lane >> 2, t4 = lane & 3;
    const int wrow = wid * 16;
    const float scale = 0.125f;

#pragma unroll
    for (int i = 0; i < 8; i++) {
        int r = i * 8 + (tid >> 4);
        int c = (tid & 15) * 4;
        float4 v = *(const float4*)(Q + base + (size_t)(qt * 64 + r) * Dm + c);
        Ps[r][c + 0] = f2tf(v.x * scale); Ps[r][c + 1] = f2tf(v.y * scale);
        Ps[r][c + 2] = f2tf(v.z * scale); Ps[r][c + 3] = f2tf(v.w * scale);
    }
    __syncthreads();

    uint32_t qa[8][4];
#pragma unroll
    for (int ks = 0; ks < 8; ks++) {
        qa[ks][0] = Ps[wrow + gid][ks * 8 + t4];
        qa[ks][1] = Ps[wrow + 8 + gid][ks * 8 + t4];
        qa[ks][2] = Ps[wrow + gid][ks * 8 + t4 + 4];
        qa[ks][3] = Ps[wrow + 8 + gid][ks * 8 + t4 + 4];
    }

    float acc[8][4];
#pragma unroll
    for (int nt = 0; nt < 8; nt++)
#pragma unroll
        for (int k = 0; k < 4; k++) acc[nt][k] = 0.f;
    float mrow0 = -INFINITY, mrow1 = -INFINITY;
    float lrow0 = 0.f, lrow1 = 0.f;

    for (int j = 0; j <= qt; j++) {
        __syncthreads();
#pragma unroll
        for (int i = 0; i < 8; i++) {
            int r = i * 8 + (tid >> 4);
            int c = (tid & 15) * 4;
            size_t off = base + (size_t)(j * 64 + r) * Dm + c;
            float4 kv = *(const float4*)(K + off);
            float4 vv = *(const float4*)(V + off);
            Ks[r][c + 0] = f2tf(kv.x); Ks[r][c + 1] = f2tf(kv.y);
            Ks[r][c + 2] = f2tf(kv.z); Ks[r][c + 3] = f2tf(kv.w);
            Vs[r][c + 0] = f2tf(vv.x); Vs[r][c + 1] = f2tf(vv.y);
            Vs[r][c + 2] = f2tf(vv.z); Vs[r][c + 3] = f2tf(vv.w);
        }
        __syncthreads();

        float s[8][4];
#pragma unroll
        for (int nt = 0; nt < 8; nt++)
#pragma unroll
            for (int k = 0; k < 4; k++) s[nt][k] = 0.f;
#pragma unroll
        for (int ks = 0; ks < 8; ks++) {
#pragma unroll
            for (int nt = 0; nt < 8; nt++) {
                uint32_t b0 = Ks[nt * 8 + gid][ks * 8 + t4];
                uint32_t b1 = Ks[nt * 8 + gid][ks * 8 + t4 + 4];
                mma_tf32(s[nt], qa[ks], b0, b1);
            }
        }

        if (j == qt) {
            int r0 = wrow + gid, r1 = wrow + gid + 8;
#pragma unroll
            for (int nt = 0; nt < 8; nt++) {
                int c0 = nt * 8 + 2 * t4;
                if (c0 > r0)     s[nt][0] = -1e30f;
                if (c0 + 1 > r0) s[nt][1] = -1e30f;
                if (c0 > r1)     s[nt][2] = -1e30f;
                if (c0 + 1 > r1) s[nt][3] = -1e30f;
            }
        }

        float mx0 = -INFINITY, mx1 = -INFINITY;
#pragma unroll
        for (int nt = 0; nt < 8; nt++) {
            mx0 = fmaxf(mx0, fmaxf(s[nt][0], s[nt][1]));
            mx1 = fmaxf(mx1, fmaxf(s[nt][2], s[nt][3]));
        }
        mx0 = fmaxf(mx0, __shfl_xor_sync(0xffffffffu, mx0, 1));
        mx0 = fmaxf(mx0, __shfl_xor_sync(0xffffffffu, mx0, 2));
        mx1 = fmaxf(mx1, __shfl_xor_sync(0xffffffffu, mx1, 1));
        mx1 = fmaxf(mx1, __shfl_xor_sync(0xffffffffu, mx1, 2));

        float mn0 = fmaxf(mrow0, mx0), mn1 = fmaxf(mrow1, mx1);
        float cor0 = __expf(mrow0 - mn0), cor1 = __expf(mrow1 - mn1);
        mrow0 = mn0; mrow1 = mn1;

        float ls0 = 0.f, ls1 = 0.f;
#pragma unroll
        for (int nt = 0; nt < 8; nt++) {
            s[nt][0] = __expf(s[nt][0] - mn0);
            s[nt][1] = __expf(s[nt][1] - mn0);
            s[nt][2] = __expf(s[nt][2] - mn1);
            s[nt][3] = __expf(s[nt][3] - mn1);
            ls0 += s[nt][0] + s[nt][1];
            ls1 += s[nt][2] + s[nt][3];
        }
        ls0 += __shfl_xor_sync(0xffffffffu, ls0, 1);
        ls0 += __shfl_xor_sync(0xffffffffu, ls0, 2);
        ls1 += __shfl_xor_sync(0xffffffffu, ls1, 1);
        ls1 += __shfl_xor_sync(0xffffffffu, ls1, 2);
        lrow0 = lrow0 * cor0 + ls0;
        lrow1 = lrow1 * cor1 + ls1;

#pragma unroll
        for (int nt = 0; nt < 8; nt++) {
            acc[nt][0] *= cor0; acc[nt][1] *= cor0;
            acc[nt][2] *= cor1; acc[nt][3] *= cor1;
        }

#pragma unroll
        for (int nt = 0; nt < 8; nt++) {
            int c0 = nt * 8 + 2 * t4;
            Ps[wrow + gid][c0]         = f2tf(s[nt][0]);
            Ps[wrow + gid][c0 + 1]     = f2tf(s[nt][1]);
            Ps[wrow + 8 + gid][c0]     = f2tf(s[nt][2]);
            Ps[wrow + 8 + gid][c0 + 1] = f2tf(s[nt][3]);
        }
        __syncwarp();

#pragma unroll
        for (int ks = 0; ks < 8; ks++) {
            uint32_t pa[4];
            pa[0] = Ps[wrow + gid][ks * 8 + t4];
            pa[1] = Ps[wrow + 8 + gid][ks * 8 + t4];
            pa[2] = Ps[wrow + gid][ks * 8 + t4 + 4];
            pa[3] = Ps[wrow + 8 + gid][ks * 8 + t4 + 4];
#pragma unroll
            for (int nt = 0; nt < 8; nt++) {
                uint32_t vb0 = Vs[ks * 8 + t4][nt * 8 + gid];
                uint32_t vb1 = Vs[ks * 8 + 4 + t4][nt * 8 + gid];
                mma_tf32(acc[nt], pa, vb0, vb1);
            }
        }
    }

    float inv0 = 1.f / lrow0, inv1 = 1.f / lrow1;
    int r0 = qt * 64 + wrow + gid;
#pragma unroll
    for (int nt = 0; nt < 8; nt++) {
        int c0 = nt * 8 + 2 * t4;
        O[base + (size_t)r0 * Dm + c0]           = acc[nt][0] * inv0;
        O[base + (size_t)r0 * Dm + c0 + 1]       = acc[nt][1] * inv0;
        O[base + (size_t)(r0 + 8) * Dm + c0]     = acc[nt][2] * inv1;
        O[base + (size_t)(r0 + 8) * Dm + c0 + 1] = acc[nt][3] * inv1;
    }
}

// ============================================================================
// Launch
// ============================================================================
extern "C" void kernel_launch(void* const* d_in, const int* in_sizes, int n_in,
                              void* d_out, int out_size) {
    const float* x  = (const float*)d_in[0];
    const float* Wq = (const float*)d_in[1];
    const float* Wk = (const float*)d_in[2];
    const float* Wv = (const float*)d_in[3];
    const float* Wo = (const float*)d_in[4];
    const float* bq = (const float*)d_in[5];
    const float* bk = (const float*)d_in[6];
    const float* bv = (const float*)d_in[7];
    const float* bo = (const float*)d_in[8];
    float* out = (float*)d_out;

    float *gq, *gk, *gv, *go;
    cudaGetSymbolAddress((void**)&gq, g_Q);
    cudaGetSymbolAddress((void**)&gk, g_K);
    cudaGetSymbolAddress((void**)&gv, g_V);
    cudaGetSymbolAddress((void**)&go, g_O);

    cudaFuncSetAttribute(attn_kernel, cudaFuncAttributeMaxDynamicSharedMemorySize,
                         ATTN_SMEM);

    dim3 gg(Dm / BN, Lb / BM, NZ);   // (8, 8, 16)
    dim3 gb(256);
    gemm_tf32<<<gg, gb>>>(x, Wq, bq, gq);
    gemm_tf32<<<gg, gb>>>(x, Wk, bk, gk);
    gemm_tf32<<<gg, gb>>>(x, Wv, bv, gv);
    attn_kernel<<<dim3(Lb / 64, NH, NZ), 128, ATTN_SMEM>>>(gq, gk, gv, go);
    gemm_tf32<<<gg, gb>>>(go, Wo, bo, out);
}

// round 7
// speedup vs baseline: 1.2042x; 1.0791x over previous
#include <cuda_runtime.h>
#include <cstdint>
#include <cmath>

// Problem constants
constexpr int Dm   = 1024;   // d_model
constexpr int Lb   = 1024;   // block length (SEQ / SPLIT)
constexpr int NSP  = 4;      // SPLIT
constexpr int NB   = 4;      // batch
constexpr int NH   = 16;     // heads
constexpr int DK   = 64;     // head dim
constexpr int NZ   = NB * NSP;  // 16 independent (b,s) blocks

// Scratch (allocation-free rule: __device__ globals)
__device__ float g_Q[(size_t)NZ * Lb * Dm];
__device__ float g_K[(size_t)NZ * Lb * Dm];
__device__ float g_V[(size_t)NZ * Lb * Dm];
__device__ float g_O[(size_t)NZ * Lb * Dm];
__device__ float g_Xc[(size_t)NZ * Lb * Dm];        // tf32-rounded x
__device__ float g_Wc[(size_t)4 * NSP * Dm * Dm];   // tf32-rounded weights

__device__ __forceinline__ uint32_t f2tf(float f) {
    uint32_t u;
    asm("cvt.rna.tf32.f32 %0, %1;" : "=r"(u) : "f"(f));
    return u;
}
__device__ __forceinline__ float f2tff(float f) {
    return __uint_as_float(f2tf(f));
}

__device__ __forceinline__ uint32_t smem_u32(const void* p) {
    uint32_t a;
    asm("{ .reg .u64 t; cvta.to.shared.u64 t, %1; cvt.u32.u64 %0, t; }"
        : "=r"(a) : "l"(p));
    return a;
}

__device__ __forceinline__ void cp16(uint32_t dst, const void* src) {
    asm volatile("cp.async.cg.shared.global [%0], [%1], 16;"
                 :: "r"(dst), "l"(src) : "memory");
}
#define CP_COMMIT() asm volatile("cp.async.commit_group;" ::: "memory")
#define CP_WAIT1()  asm volatile("cp.async.wait_group 1;" ::: "memory")

__device__ __forceinline__ void mma_tf32(float c[4], const uint32_t a[4],
                                         uint32_t b0, uint32_t b1) {
    asm volatile(
        "mma.sync.aligned.m16n8k8.row.col.f32.tf32.tf32.f32 "
        "{%0,%1,%2,%3}, {%4,%5,%6,%7}, {%8,%9}, {%0,%1,%2,%3};\n"
        : "+f"(c[0]), "+f"(c[1]), "+f"(c[2]), "+f"(c[3])
        : "r"(a[0]), "r"(a[1]), "r"(a[2]), "r"(a[3]), "r"(b0), "r"(b1));
}

// ============================================================================
// Elementwise tf32 rounding (one-time prep): dst[i] = tf32(src[i])
// ============================================================================
__global__ __launch_bounds__(256) void convert_tf32(const float* __restrict__ src,
                                                    float* __restrict__ dst) {
    size_t i = (size_t)blockIdx.x * 256 + threadIdx.x;
    float4 v = ((const float4*)src)[i];
    v.x = f2tff(v.x); v.y = f2tff(v.y); v.z = f2tff(v.z); v.w = f2tff(v.w);
    ((float4*)dst)[i] = v;
}

// ============================================================================
// GEMM: C[z] = X[z] @ W[z%NSP] + bias[z%NSP]
// Inputs pre-rounded to tf32 -> raw-byte cp.async 3-stage pipeline, no cvt/STS
// in the hot loop. 128 threads = 4 warps of 64x64 output each (tile 128x128).
// TF32OUT: round outputs to tf32 (for Q/K/V feeding attention).
// ============================================================================
constexpr int A_STR   = 36;                 // uint32 per A row (pad: conflict-free)
constexpr int B_STR   = 132;                // uint32 per B k-row
constexpr int STAGE_A = 128 * A_STR;        // 4608 words
constexpr int STAGE_B = 32 * B_STR;         // 4224 words
constexpr int STAGE_W = STAGE_A + STAGE_B;  // 8832 words = 35328 B
constexpr int NSTAGE  = 3;
constexpr int GEMM_SMEM_B = NSTAGE * STAGE_W * 4;   // 105984 B

template <bool TF32OUT>
__global__ __launch_bounds__(128) void gemm_tc(const float* __restrict__ X,
                                               const float* __restrict__ W,
                                               const float* __restrict__ bias,
                                               float* __restrict__ C) {
    extern __shared__ uint32_t smw[];
    const uint32_t sb = smem_u32(smw);

    const int z = blockIdx.z;
    const int m0 = blockIdx.y * 128, n0 = blockIdx.x * 128;
    const float* Xb = X + (size_t)z * Lb * Dm + (size_t)m0 * Dm;
    const float* Wb = W + (size_t)(z % NSP) * Dm * Dm + n0;
    const float* bb = bias + (size_t)(z % NSP) * Dm + n0;
    float* Cb = C + (size_t)z * Lb * Dm + (size_t)m0 * Dm + n0;

    const int tid = threadIdx.x;
    const int wid = tid >> 5, lane = tid & 31;
    const int gid = lane >> 2, t4 = lane & 3;
    const int wm = (wid & 1) * 64;      // 2 warps along M
    const int wn = (wid >> 1) * 64;     // 2 warps along N

    // staging: 16 cp.async of 16B per thread per chunk
    const int arow = tid >> 3, ac4 = tid & 7;     // A: 16 rows/pass x 8 cols
    const int bkr  = tid >> 5, bc4 = tid & 31;    // B: 4 k-rows/pass x 32 cols
    auto stage = [&](int c) {
        uint32_t base = sb + (uint32_t)(c % NSTAGE) * (STAGE_W * 4);
        const float* xa = Xb + c * 32;
        const float* wa = Wb + (size_t)c * 32 * Dm;
#pragma unroll
        for (int i = 0; i < 8; i++) {
            int r = arow + i * 16;
            cp16(base + (uint32_t)(r * A_STR + ac4 * 4) * 4,
                 xa + (size_t)r * Dm + ac4 * 4);
        }
#pragma unroll
        for (int i = 0; i < 8; i++) {
            int kr = bkr + i * 4;
            cp16(base + (uint32_t)(STAGE_A + kr * B_STR + bc4 * 4) * 4,
                 wa + (size_t)kr * Dm + bc4 * 4);
        }
    };

    float acc[4][8][4];
#pragma unroll
    for (int i = 0; i < 4; i++)
#pragma unroll
        for (int j = 0; j < 8; j++)
#pragma unroll
            for (int k = 0; k < 4; k++) acc[i][j][k] = 0.f;

    stage(0); CP_COMMIT();
    stage(1); CP_COMMIT();

    const int NCHUNK = Dm / 32;   // 32
    for (int c = 0; c < NCHUNK; c++) {
        CP_WAIT1();
        __syncthreads();

        const uint32_t* SA = smw + (c % NSTAGE) * STAGE_W;
        const uint32_t* SB = SA + STAGE_A;
#pragma unroll
        for (int kk = 0; kk < 32; kk += 8) {
            uint32_t af[4][4], bf[8][2];
#pragma unroll
            for (int mt = 0; mt < 4; mt++) {
                int r0 = (wm + mt * 16 + gid) * A_STR;
                af[mt][0] = SA[r0 + kk + t4];
                af[mt][1] = SA[r0 + 8 * A_STR + kk + t4];
                af[mt][2] = SA[r0 + kk + t4 + 4];
                af[mt][3] = SA[r0 + 8 * A_STR + kk + t4 + 4];
            }
#pragma unroll
            for (int nt = 0; nt < 8; nt++) {
                int cb = wn + nt * 8 + gid;
                bf[nt][0] = SB[(kk + t4) * B_STR + cb];
                bf[nt][1] = SB[(kk + 4 + t4) * B_STR + cb];
            }
#pragma unroll
            for (int mt = 0; mt < 4; mt++)
#pragma unroll
                for (int nt = 0; nt < 8; nt++)
                    mma_tf32(acc[mt][nt], af[mt], bf[nt][0], bf[nt][1]);
        }
        __syncthreads();
        if (c + 2 < NCHUNK) stage(c + 2);
        CP_COMMIT();
    }

    // Epilogue: + bias (optionally tf32-round for attention consumers)
#pragma unroll
    for (int mt = 0; mt < 4; mt++) {
        int r0 = wm + mt * 16 + gid;
#pragma unroll
        for (int nt = 0; nt < 8; nt++) {
            int c0 = wn + nt * 8 + 2 * t4;
            float bv0 = bb[c0], bv1 = bb[c0 + 1];
            float v0 = acc[mt][nt][0] + bv0, v1 = acc[mt][nt][1] + bv1;
            float v2 = acc[mt][nt][2] + bv0, v3 = acc[mt][nt][3] + bv1;
            if (TF32OUT) {
                v0 = f2tff(v0); v1 = f2tff(v1); v2 = f2tff(v2); v3 = f2tff(v3);
            }
            *(float2*)(Cb + (size_t)r0 * Dm + c0)       = make_float2(v0, v1);
            *(float2*)(Cb + (size_t)(r0 + 8) * Dm + c0) = make_float2(v2, v3);
        }
    }
}

// ============================================================================
// Flash attention per (z, h). Inputs Q/K/V are tf32-rounded already ->
// raw vectorized staging (no cvt). Output written tf32-rounded for O-proj.
// ============================================================================
constexpr int KS_STR = 68;
constexpr int VS_STR = 72;
constexpr int ATTN_SMEM = 64 * (KS_STR + VS_STR + KS_STR) * 4;  // 53248 B

__global__ __launch_bounds__(128) void attn_kernel(const float* __restrict__ Q,
                                                   const float* __restrict__ K,
                                                   const float* __restrict__ V,
                                                   float* __restrict__ O) {
    extern __shared__ uint32_t sm[];
    uint32_t (*Ks)[KS_STR] = (uint32_t(*)[KS_STR])sm;
    uint32_t (*Vs)[VS_STR] = (uint32_t(*)[VS_STR])(sm + 64 * KS_STR);
    uint32_t (*Ps)[KS_STR] = (uint32_t(*)[KS_STR])(sm + 64 * KS_STR + 64 * VS_STR);

    const int qt = blockIdx.x;
    const int h  = blockIdx.y;
    const int z  = blockIdx.z;
    const size_t base = (size_t)z * Lb * Dm + h * DK;

    const int tid = threadIdx.x;
    const int wid = tid >> 5, lane = tid & 31;
    const int gid = lane >> 2, t4 = lane & 3;
    const int wrow = wid * 16;
    const float scale = 0.125f;    // exact pow2: Q*scale stays tf32-exact

#pragma unroll
    for (int i = 0; i < 8; i++) {
        int r = i * 8 + (tid >> 4);
        int c = (tid & 15) * 4;
        float4 v = *(const float4*)(Q + base + (size_t)(qt * 64 + r) * Dm + c);
        v.x *= scale; v.y *= scale; v.z *= scale; v.w *= scale;
        *(float4*)&Ps[r][c] = v;
    }
    __syncthreads();

    uint32_t qa[8][4];
#pragma unroll
    for (int ks = 0; ks < 8; ks++) {
        qa[ks][0] = Ps[wrow + gid][ks * 8 + t4];
        qa[ks][1] = Ps[wrow + 8 + gid][ks * 8 + t4];
        qa[ks][2] = Ps[wrow + gid][ks * 8 + t4 + 4];
        qa[ks][3] = Ps[wrow + 8 + gid][ks * 8 + t4 + 4];
    }

    float acc[8][4];
#pragma unroll
    for (int nt = 0; nt < 8; nt++)
#pragma unroll
        for (int k = 0; k < 4; k++) acc[nt][k] = 0.f;
    float mrow0 = -INFINITY, mrow1 = -INFINITY;
    float lrow0 = 0.f, lrow1 = 0.f;

    for (int j = 0; j <= qt; j++) {
        __syncthreads();
#pragma unroll
        for (int i = 0; i < 8; i++) {
            int r = i * 8 + (tid >> 4);
            int c = (tid & 15) * 4;
            size_t off = base + (size_t)(j * 64 + r) * Dm + c;
            *(uint4*)&Ks[r][c] = *(const uint4*)(K + off);
            *(uint4*)&Vs[r][c] = *(const uint4*)(V + off);
        }
        __syncthreads();

        float s[8][4];
#pragma unroll
        for (int nt = 0; nt < 8; nt++)
#pragma unroll
            for (int k = 0; k < 4; k++) s[nt][k] = 0.f;
#pragma unroll
        for (int ks = 0; ks < 8; ks++) {
#pragma unroll
            for (int nt = 0; nt < 8; nt++) {
                uint32_t b0 = Ks[nt * 8 + gid][ks * 8 + t4];
                uint32_t b1 = Ks[nt * 8 + gid][ks * 8 + t4 + 4];
                mma_tf32(s[nt], qa[ks], b0, b1);
            }
        }

        if (j == qt) {
            int r0 = wrow + gid, r1 = wrow + gid + 8;
#pragma unroll
            for (int nt = 0; nt < 8; nt++) {
                int c0 = nt * 8 + 2 * t4;
                if (c0 > r0)     s[nt][0] = -1e30f;
                if (c0 + 1 > r0) s[nt][1] = -1e30f;
                if (c0 > r1)     s[nt][2] = -1e30f;
                if (c0 + 1 > r1) s[nt][3] = -1e30f;
            }
        }

        float mx0 = -INFINITY, mx1 = -INFINITY;
#pragma unroll
        for (int nt = 0; nt < 8; nt++) {
            mx0 = fmaxf(mx0, fmaxf(s[nt][0], s[nt][1]));
            mx1 = fmaxf(mx1, fmaxf(s[nt][2], s[nt][3]));
        }
        mx0 = fmaxf(mx0, __shfl_xor_sync(0xffffffffu, mx0, 1));
        mx0 = fmaxf(mx0, __shfl_xor_sync(0xffffffffu, mx0, 2));
        mx1 = fmaxf(mx1, __shfl_xor_sync(0xffffffffu, mx1, 1));
        mx1 = fmaxf(mx1, __shfl_xor_sync(0xffffffffu, mx1, 2));

        float mn0 = fmaxf(mrow0, mx0), mn1 = fmaxf(mrow1, mx1);
        float cor0 = __expf(mrow0 - mn0), cor1 = __expf(mrow1 - mn1);
        mrow0 = mn0; mrow1 = mn1;

        float ls0 = 0.f, ls1 = 0.f;
#pragma unroll
        for (int nt = 0; nt < 8; nt++) {
            s[nt][0] = __expf(s[nt][0] - mn0);
            s[nt][1] = __expf(s[nt][1] - mn0);
            s[nt][2] = __expf(s[nt][2] - mn1);
            s[nt][3] = __expf(s[nt][3] - mn1);
            ls0 += s[nt][0] + s[nt][1];
            ls1 += s[nt][2] + s[nt][3];
        }
        ls0 += __shfl_xor_sync(0xffffffffu, ls0, 1);
        ls0 += __shfl_xor_sync(0xffffffffu, ls0, 2);
        ls1 += __shfl_xor_sync(0xffffffffu, ls1, 1);
        ls1 += __shfl_xor_sync(0xffffffffu, ls1, 2);
        lrow0 = lrow0 * cor0 + ls0;
        lrow1 = lrow1 * cor1 + ls1;

#pragma unroll
        for (int nt = 0; nt < 8; nt++) {
            acc[nt][0] *= cor0; acc[nt][1] *= cor0;
            acc[nt][2] *= cor1; acc[nt][3] *= cor1;
        }

#pragma unroll
        for (int nt = 0; nt < 8; nt++) {
            int c0 = nt * 8 + 2 * t4;
            Ps[wrow + gid][c0]         = f2tf(s[nt][0]);
            Ps[wrow + gid][c0 + 1]     = f2tf(s[nt][1]);
            Ps[wrow + 8 + gid][c0]     = f2tf(s[nt][2]);
            Ps[wrow + 8 + gid][c0 + 1] = f2tf(s[nt][3]);
        }
        __syncwarp();

#pragma unroll
        for (int ks = 0; ks < 8; ks++) {
            uint32_t pa[4];
            pa[0] = Ps[wrow + gid][ks * 8 + t4];
            pa[1] = Ps[wrow + 8 + gid][ks * 8 + t4];
            pa[2] = Ps[wrow + gid][ks * 8 + t4 + 4];
            pa[3] = Ps[wrow + 8 + gid][ks * 8 + t4 + 4];
#pragma unroll
            for (int nt = 0; nt < 8; nt++) {
                uint32_t vb0 = Vs[ks * 8 + t4][nt * 8 + gid];
                uint32_t vb1 = Vs[ks * 8 + 4 + t4][nt * 8 + gid];
                mma_tf32(acc[nt], pa, vb0, vb1);
            }
        }
    }

    // Finalize: divide by row sums, write tf32-rounded O (feeds O-projection)
    float inv0 = 1.f / lrow0, inv1 = 1.f / lrow1;
    int r0 = qt * 64 + wrow + gid;
#pragma unroll
    for (int nt = 0; nt < 8; nt++) {
        int c0 = nt * 8 + 2 * t4;
        O[base + (size_t)r0 * Dm + c0]           = f2tff(acc[nt][0] * inv0);
        O[base + (size_t)r0 * Dm + c0 + 1]       = f2tff(acc[nt][1] * inv0);
        O[base + (size_t)(r0 + 8) * Dm + c0]     = f2tff(acc[nt][2] * inv1);
        O[base + (size_t)(r0 + 8) * Dm + c0 + 1] = f2tff(acc[nt][3] * inv1);
    }
}

// ============================================================================
// Launch
// ============================================================================
extern "C" void kernel_launch(void* const* d_in, const int* in_sizes, int n_in,
                              void* d_out, int out_size) {
    const float* x  = (const float*)d_in[0];
    const float* Wq = (const float*)d_in[1];
    const float* Wk = (const float*)d_in[2];
    const float* Wv = (const float*)d_in[3];
    const float* Wo = (const float*)d_in[4];
    const float* bq = (const float*)d_in[5];
    const float* bk = (const float*)d_in[6];
    const float* bv = (const float*)d_in[7];
    const float* bo = (const float*)d_in[8];
    float* out = (float*)d_out;

    float *gq, *gk, *gv, *go, *gxc, *gwc;
    cudaGetSymbolAddress((void**)&gq, g_Q);
    cudaGetSymbolAddress((void**)&gk, g_K);
    cudaGetSymbolAddress((void**)&gv, g_V);
    cudaGetSymbolAddress((void**)&go, g_O);
    cudaGetSymbolAddress((void**)&gxc, g_Xc);
    cudaGetSymbolAddress((void**)&gwc, g_Wc);
    const size_t WSZ = (size_t)NSP * Dm * Dm;   // 4.19M floats per weight set

    cudaFuncSetAttribute(attn_kernel, cudaFuncAttributeMaxDynamicSharedMemorySize,
                         ATTN_SMEM);
    cudaFuncSetAttribute(gemm_tc<true>, cudaFuncAttributeMaxDynamicSharedMemorySize,
                         GEMM_SMEM_B);
    cudaFuncSetAttribute(gemm_tc<false>, cudaFuncAttributeMaxDynamicSharedMemorySize,
                         GEMM_SMEM_B);

    // tf32 pre-rounding (one elementwise pass; float4 granularity)
    const size_t XQ = (size_t)NZ * Lb * Dm / 4;   // float4 count
    const size_t WQ4 = WSZ / 4;
    convert_tf32<<<(unsigned)(XQ / 256), 256>>>(x, gxc);
    convert_tf32<<<(unsigned)(WQ4 / 256), 256>>>(Wq, gwc);
    convert_tf32<<<(unsigned)(WQ4 / 256), 256>>>(Wk, gwc + WSZ);
    convert_tf32<<<(unsigned)(WQ4 / 256), 256>>>(Wv, gwc + 2 * WSZ);
    convert_tf32<<<(unsigned)(WQ4 / 256), 256>>>(Wo, gwc + 3 * WSZ);

    dim3 gg(Dm / 128, Lb / 128, NZ);   // (8, 8, 16)
    gemm_tc<true><<<gg, 128, GEMM_SMEM_B>>>(gxc, gwc,           bq, gq);
    gemm_tc<true><<<gg, 128, GEMM_SMEM_B>>>(gxc, gwc + WSZ,     bk, gk);
    gemm_tc<true><<<gg, 128, GEMM_SMEM_B>>>(gxc, gwc + 2 * WSZ, bv, gv);
    attn_kernel<<<dim3(Lb / 64, NH, NZ), 128, ATTN_SMEM>>>(gq, gk, gv, go);
    gemm_tc<false><<<gg, 128, GEMM_SMEM_B>>>(go, gwc + 3 * WSZ, bo, out);
}

// round 8
// speedup vs baseline: 1.3111x; 1.0887x over previous
#include <cuda_runtime.h>
#include <cstdint>
#include <cmath>

// Problem constants
constexpr int Dm   = 1024;   // d_model
constexpr int Lb   = 1024;   // block length (SEQ / SPLIT)
constexpr int NSP  = 4;      // SPLIT
constexpr int NB   = 4;      // batch
constexpr int NH   = 16;     // heads
constexpr int DK   = 64;     // head dim
constexpr int NZ   = NB * NSP;  // 16 independent (b,s) blocks

// Scratch (allocation-free rule: __device__ globals)
__device__ float g_Q[(size_t)NZ * Lb * Dm];
__device__ float g_K[(size_t)NZ * Lb * Dm];
__device__ float g_V[(size_t)NZ * Lb * Dm];
__device__ float g_O[(size_t)NZ * Lb * Dm];      // k-interleave permuted layout
__device__ float g_Xc[(size_t)NZ * Lb * Dm];     // tf32-rounded, k-interleave permuted
__device__ float g_Wc[(size_t)4 * NSP * Dm * Dm];// tf32-rounded weights (plain layout)

// k-interleave permutation within each 8-column group:
//   logical l (0..7) -> phys p = (l<4) ? 2l : 2(l-4)+1
// A-side (x, g_O): permuted in GLOBAL memory. B-side (W): rows permuted at staging.

__device__ __forceinline__ uint32_t f2tf(float f) {
    uint32_t u;
    asm("cvt.rna.tf32.f32 %0, %1;" : "=r"(u) : "f"(f));
    return u;
}
__device__ __forceinline__ float f2tff(float f) {
    return __uint_as_float(f2tf(f));
}

__device__ __forceinline__ uint32_t smem_u32(const void* p) {
    uint32_t a;
    asm("{ .reg .u64 t; cvta.to.shared.u64 t, %1; cvt.u32.u64 %0, t; }"
        : "=r"(a) : "l"(p));
    return a;
}

__device__ __forceinline__ void cp16(uint32_t dst, const void* src) {
    asm volatile("cp.async.cg.shared.global [%0], [%1], 16;"
                 :: "r"(dst), "l"(src) : "memory");
}
#define CP_COMMIT() asm volatile("cp.async.commit_group;" ::: "memory")
#define CP_WAIT1()  asm volatile("cp.async.wait_group 1;" ::: "memory")

__device__ __forceinline__ void mma_tf32(float c[4], const uint32_t a[4],
                                         uint32_t b0, uint32_t b1) {
    asm volatile(
        "mma.sync.aligned.m16n8k8.row.col.f32.tf32.tf32.f32 "
        "{%0,%1,%2,%3}, {%4,%5,%6,%7}, {%8,%9}, {%0,%1,%2,%3};\n"
        : "+f"(c[0]), "+f"(c[1]), "+f"(c[2]), "+f"(c[3])
        : "r"(a[0]), "r"(a[1]), "r"(a[2]), "r"(a[3]), "r"(b0), "r"(b1));
}

// ============================================================================
// Converts (one-time prep)
// ============================================================================
// x: tf32-round AND k-interleave permute each 8-col group.
// phys [0..7] = logical [0,4,1,5,2,6,3,7]
__global__ __launch_bounds__(256) void convert_x_perm(const float* __restrict__ src,
                                                      float* __restrict__ dst) {
    size_t g = (size_t)blockIdx.x * 256 + threadIdx.x;   // 8-float group index
    const float4* s = (const float4*)src + g * 2;
    float4 a = s[0], b = s[1];                            // logical 0..3, 4..7
    float4 lo = make_float4(f2tff(a.x), f2tff(b.x), f2tff(a.y), f2tff(b.y));
    float4 hi = make_float4(f2tff(a.z), f2tff(b.z), f2tff(a.w), f2tff(b.w));
    ((float4*)dst)[g * 2]     = lo;
    ((float4*)dst)[g * 2 + 1] = hi;
}

// W: plain tf32 rounding, 4 weight sets in one launch (grid.z selects)
__global__ __launch_bounds__(256) void convert_w(const float* __restrict__ w0,
                                                 const float* __restrict__ w1,
                                                 const float* __restrict__ w2,
                                                 const float* __restrict__ w3,
                                                 float* __restrict__ dst) {
    const int p = blockIdx.z;
    const float* src = (p == 0) ? w0 : (p == 1) ? w1 : (p == 2) ? w2 : w3;
    float* d = dst + (size_t)p * NSP * Dm * Dm;
    size_t i = (size_t)blockIdx.x * 256 + threadIdx.x;
    float4 v = ((const float4*)src)[i];
    v.x = f2tff(v.x); v.y = f2tff(v.y); v.z = f2tff(v.z); v.w = f2tff(v.w);
    ((float4*)d)[i] = v;
}

// ============================================================================
// GEMM core: C[z] = X[z] @ W + bias. 128 threads, 4 warps x 64x64 tile.
// cp.async 3-stage pipeline, single barrier/chunk. A in permuted layout
// (LDS.64 frag reads, A_STR=40 conflict-free); W k-rows permuted at staging
// so B frag rows are 2t4/2t4+1 (B_STR=132 -> banks 8t4+gid, conflict-free).
// ============================================================================
constexpr int A_STR   = 40;                  // uint32 per A row
constexpr int B_STR   = 132;                 // uint32 per B k-row
constexpr int STAGE_AW = 128 * A_STR;        // 5120 words
constexpr int STAGE_BW = 32 * B_STR;         // 4224 words
constexpr int STAGE_W  = STAGE_AW + STAGE_BW;// 9344 words = 37376 B
constexpr int NSTAGE   = 3;
constexpr int GEMM_SMEM_B = NSTAGE * STAGE_W * 4;   // 112128 B (2 CTAs/SM)

template <bool TF32OUT>
__device__ __forceinline__ void gemm_core(const float* __restrict__ Xz,
                                          const float* __restrict__ Wz,
                                          const float* __restrict__ bz,
                                          float* __restrict__ Cz,
                                          uint32_t* smw) {
    const uint32_t sb = smem_u32(smw);
    const int m0 = blockIdx.y * 128, n0 = blockIdx.x * 128;
    const float* Xb = Xz + (size_t)m0 * Dm;
    const float* Wb = Wz + n0;
    const float* bb = bz + n0;
    float* Cb = Cz + (size_t)m0 * Dm + n0;

    const int tid = threadIdx.x;
    const int wid = tid >> 5, lane = tid & 31;
    const int gid = lane >> 2, t4 = lane & 3;
    const int wm = (wid & 1) * 64, wn = (wid >> 1) * 64;

    const int arow = tid >> 3, ac4 = tid & 7;
    const int bkr  = tid >> 5, bc4 = tid & 31;

    auto stage = [&](int c) {
        uint32_t base = sb + (uint32_t)(c % NSTAGE) * (STAGE_W * 4);
        const float* xa = Xb + c * 32;
        const float* wa = Wb + (size_t)c * 32 * Dm;
#pragma unroll
        for (int i = 0; i < 8; i++) {
            int r = arow + i * 16;
            cp16(base + (uint32_t)(r * A_STR + ac4 * 4) * 4,
                 xa + (size_t)r * Dm + ac4 * 4);
        }
#pragma unroll
        for (int i = 0; i < 8; i++) {
            int kr = bkr + i * 4;               // logical k-row 0..31
            int l = kr & 7;
            int kp = (kr & ~7) | ((l < 4) ? 2 * l : 2 * (l - 4) + 1);
            cp16(base + (uint32_t)(STAGE_AW + kp * B_STR + bc4 * 4) * 4,
                 wa + (size_t)kr * Dm + bc4 * 4);
        }
    };

    float acc[4][8][4];
#pragma unroll
    for (int i = 0; i < 4; i++)
#pragma unroll
        for (int j = 0; j < 8; j++)
#pragma unroll
            for (int k = 0; k < 4; k++) acc[i][j][k] = 0.f;

    stage(0); CP_COMMIT();
    stage(1); CP_COMMIT();

    const int NCHUNK = Dm / 32;   // 32
    for (int c = 0; c < NCHUNK; c++) {
        CP_WAIT1();
        __syncthreads();          // single barrier: also protects buffer reuse
        if (c + 2 < NCHUNK) stage(c + 2);
        CP_COMMIT();

        const uint32_t* SA = smw + (c % NSTAGE) * STAGE_W;
        const uint32_t* SB = SA + STAGE_AW;
#pragma unroll
        for (int kk = 0; kk < 32; kk += 8) {
            uint32_t af[4][4], bf[8][2];
#pragma unroll
            for (int mt = 0; mt < 4; mt++) {
                int r0 = (wm + mt * 16 + gid) * A_STR;
                uint2 u0 = *(const uint2*)&SA[r0 + kk + 2 * t4];
                uint2 u1 = *(const uint2*)&SA[r0 + 8 * A_STR + kk + 2 * t4];
                af[mt][0] = u0.x; af[mt][1] = u1.x;
                af[mt][2] = u0.y; af[mt][3] = u1.y;
            }
#pragma unroll
            for (int nt = 0; nt < 8; nt++) {
                int cb = wn + nt * 8 + gid;
                bf[nt][0] = SB[(kk + 2 * t4) * B_STR + cb];       // logical k=t4
                bf[nt][1] = SB[(kk + 2 * t4 + 1) * B_STR + cb];   // logical k=t4+4
            }
#pragma unroll
            for (int mt = 0; mt < 4; mt++)
#pragma unroll
                for (int nt = 0; nt < 8; nt++)
                    mma_tf32(acc[mt][nt], af[mt], bf[nt][0], bf[nt][1]);
        }
    }

    // Epilogue: + bias (TF32OUT rounds for attention consumers); logical layout
#pragma unroll
    for (int mt = 0; mt < 4; mt++) {
        int r0 = wm + mt * 16 + gid;
#pragma unroll
        for (int nt = 0; nt < 8; nt++) {
            int c0 = wn + nt * 8 + 2 * t4;
            float bv0 = bb[c0], bv1 = bb[c0 + 1];
            float v0 = acc[mt][nt][0] + bv0, v1 = acc[mt][nt][1] + bv1;
            float v2 = acc[mt][nt][2] + bv0, v3 = acc[mt][nt][3] + bv1;
            if (TF32OUT) {
                v0 = f2tff(v0); v1 = f2tff(v1); v2 = f2tff(v2); v3 = f2tff(v3);
            }
            *(float2*)(Cb + (size_t)r0 * Dm + c0)       = make_float2(v0, v1);
            *(float2*)(Cb + (size_t)(r0 + 8) * Dm + c0) = make_float2(v2, v3);
        }
    }
}

// Fused Q/K/V projection: grid.z = 3*NZ (proj-major for W L2 reuse)
__global__ __launch_bounds__(128) void gemm_qkv(const float* __restrict__ X,
                                                const float* __restrict__ Wc,
                                                const float* __restrict__ bq,
                                                const float* __restrict__ bk,
                                                const float* __restrict__ bv,
                                                float* __restrict__ Qo,
                                                float* __restrict__ Ko,
                                                float* __restrict__ Vo) {
    extern __shared__ uint32_t smw[];
    const int proj = blockIdx.z / NZ;
    const int z    = blockIdx.z % NZ;
    const size_t WSZ = (size_t)NSP * Dm * Dm;
    const float* Xz = X + (size_t)z * Lb * Dm;
    const float* Wz = Wc + proj * WSZ + (size_t)(z % NSP) * Dm * Dm;
    const float* bz = ((proj == 0) ? bq : (proj == 1) ? bk : bv)
                      + (size_t)(z % NSP) * Dm;
    float* Cz = ((proj == 0) ? Qo : (proj == 1) ? Ko : Vo) + (size_t)z * Lb * Dm;
    gemm_core<true>(Xz, Wz, bz, Cz, smw);
}

// O projection (A = g_O in permuted layout; output logical)
__global__ __launch_bounds__(128) void gemm_o(const float* __restrict__ X,
                                              const float* __restrict__ Wz4,
                                              const float* __restrict__ bo,
                                              float* __restrict__ out) {
    extern __shared__ uint32_t smw[];
    const int z = blockIdx.z;
    gemm_core<false>(X + (size_t)z * Lb * Dm,
                     Wz4 + (size_t)(z % NSP) * Dm * Dm,
                     bo + (size_t)(z % NSP) * Dm,
                     out + (size_t)z * Lb * Dm, smw);
}

// ============================================================================
// Flash attention per (z, h). Q/K/V logical tf32 values; O written in the
// k-interleave PERMUTED layout (feeds gemm_o's A side).
// ============================================================================
constexpr int KS_STR = 68;
constexpr int VS_STR = 72;
constexpr int ATTN_SMEM = 64 * (KS_STR + VS_STR + KS_STR) * 4;  // 53248 B

__global__ __launch_bounds__(128) void attn_kernel(const float* __restrict__ Q,
                                                   const float* __restrict__ K,
                                                   const float* __restrict__ V,
                                                   float* __restrict__ O) {
    extern __shared__ uint32_t sm[];
    uint32_t (*Ks)[KS_STR] = (uint32_t(*)[KS_STR])sm;
    uint32_t (*Vs)[VS_STR] = (uint32_t(*)[VS_STR])(sm + 64 * KS_STR);
    uint32_t (*Ps)[KS_STR] = (uint32_t(*)[KS_STR])(sm + 64 * KS_STR + 64 * VS_STR);

    const int qt = blockIdx.x;
    const int h  = blockIdx.y;
    const int z  = blockIdx.z;
    const size_t base = (size_t)z * Lb * Dm + h * DK;

    const int tid = threadIdx.x;
    const int wid = tid >> 5, lane = tid & 31;
    const int gid = lane >> 2, t4 = lane & 3;
    const int wrow = wid * 16;
    const float scale = 0.125f;    // exact pow2: stays tf32-exact

#pragma unroll
    for (int i = 0; i < 8; i++) {
        int r = i * 8 + (tid >> 4);
        int c = (tid & 15) * 4;
        float4 v = *(const float4*)(Q + base + (size_t)(qt * 64 + r) * Dm + c);
        v.x *= scale; v.y *= scale; v.z *= scale; v.w *= scale;
        *(float4*)&Ps[r][c] = v;
    }
    __syncthreads();

    uint32_t qa[8][4];
#pragma unroll
    for (int ks = 0; ks < 8; ks++) {
        qa[ks][0] = Ps[wrow + gid][ks * 8 + t4];
        qa[ks][1] = Ps[wrow + 8 + gid][ks * 8 + t4];
        qa[ks][2] = Ps[wrow + gid][ks * 8 + t4 + 4];
        qa[ks][3] = Ps[wrow + 8 + gid][ks * 8 + t4 + 4];
    }

    float acc[8][4];
#pragma unroll
    for (int nt = 0; nt < 8; nt++)
#pragma unroll
        for (int k = 0; k < 4; k++) acc[nt][k] = 0.f;
    float mrow0 = -INFINITY, mrow1 = -INFINITY;
    float lrow0 = 0.f, lrow1 = 0.f;

    for (int j = 0; j <= qt; j++) {
        __syncthreads();
#pragma unroll
        for (int i = 0; i < 8; i++) {
            int r = i * 8 + (tid >> 4);
            int c = (tid & 15) * 4;
            size_t off = base + (size_t)(j * 64 + r) * Dm + c;
            *(uint4*)&Ks[r][c] = *(const uint4*)(K + off);
            *(uint4*)&Vs[r][c] = *(const uint4*)(V + off);
        }
        __syncthreads();

        float s[8][4];
#pragma unroll
        for (int nt = 0; nt < 8; nt++)
#pragma unroll
            for (int k = 0; k < 4; k++) s[nt][k] = 0.f;
#pragma unroll
        for (int ks = 0; ks < 8; ks++) {
#pragma unroll
            for (int nt = 0; nt < 8; nt++) {
                uint32_t b0 = Ks[nt * 8 + gid][ks * 8 + t4];
                uint32_t b1 = Ks[nt * 8 + gid][ks * 8 + t4 + 4];
                mma_tf32(s[nt], qa[ks], b0, b1);
            }
        }

        if (j == qt) {
            int r0 = wrow + gid, r1 = wrow + gid + 8;
#pragma unroll
            for (int nt = 0; nt < 8; nt++) {
                int c0 = nt * 8 + 2 * t4;
                if (c0 > r0)     s[nt][0] = -1e30f;
                if (c0 + 1 > r0) s[nt][1] = -1e30f;
                if (c0 > r1)     s[nt][2] = -1e30f;
                if (c0 + 1 > r1) s[nt][3] = -1e30f;
            }
        }

        float mx0 = -INFINITY, mx1 = -INFINITY;
#pragma unroll
        for (int nt = 0; nt < 8; nt++) {
            mx0 = fmaxf(mx0, fmaxf(s[nt][0], s[nt][1]));
            mx1 = fmaxf(mx1, fmaxf(s[nt][2], s[nt][3]));
        }
        mx0 = fmaxf(mx0, __shfl_xor_sync(0xffffffffu, mx0, 1));
        mx0 = fmaxf(mx0, __shfl_xor_sync(0xffffffffu, mx0, 2));
        mx1 = fmaxf(mx1, __shfl_xor_sync(0xffffffffu, mx1, 1));
        mx1 = fmaxf(mx1, __shfl_xor_sync(0xffffffffu, mx1, 2));

        float mn0 = fmaxf(mrow0, mx0), mn1 = fmaxf(mrow1, mx1);
        float cor0 = __expf(mrow0 - mn0), cor1 = __expf(mrow1 - mn1);
        mrow0 = mn0; mrow1 = mn1;

        float ls0 = 0.f, ls1 = 0.f;
#pragma unroll
        for (int nt = 0; nt < 8; nt++) {
            s[nt][0] = __expf(s[nt][0] - mn0);
            s[nt][1] = __expf(s[nt][1] - mn0);
            s[nt][2] = __expf(s[nt][2] - mn1);
            s[nt][3] = __expf(s[nt][3] - mn1);
            ls0 += s[nt][0] + s[nt][1];
            ls1 += s[nt][2] + s[nt][3];
        }
        ls0 += __shfl_xor_sync(0xffffffffu, ls0, 1);
        ls0 += __shfl_xor_sync(0xffffffffu, ls0, 2);
        ls1 += __shfl_xor_sync(0xffffffffu, ls1, 1);
        ls1 += __shfl_xor_sync(0xffffffffu, ls1, 2);
        lrow0 = lrow0 * cor0 + ls0;
        lrow1 = lrow1 * cor1 + ls1;

#pragma unroll
        for (int nt = 0; nt < 8; nt++) {
            acc[nt][0] *= cor0; acc[nt][1] *= cor0;
            acc[nt][2] *= cor1; acc[nt][3] *= cor1;
        }

#pragma unroll
        for (int nt = 0; nt < 8; nt++) {
            int c0 = nt * 8 + 2 * t4;
            Ps[wrow + gid][c0]         = f2tf(s[nt][0]);
            Ps[wrow + gid][c0 + 1]     = f2tf(s[nt][1]);
            Ps[wrow + 8 + gid][c0]     = f2tf(s[nt][2]);
            Ps[wrow + 8 + gid][c0 + 1] = f2tf(s[nt][3]);
        }
        __syncwarp();

#pragma unroll
        for (int ks = 0; ks < 8; ks++) {
            uint32_t pa[4];
            pa[0] = Ps[wrow + gid][ks * 8 + t4];
            pa[1] = Ps[wrow + 8 + gid][ks * 8 + t4];
            pa[2] = Ps[wrow + gid][ks * 8 + t4 + 4];
            pa[3] = Ps[wrow + 8 + gid][ks * 8 + t4 + 4];
#pragma unroll
            for (int nt = 0; nt < 8; nt++) {
                uint32_t vb0 = Vs[ks * 8 + t4][nt * 8 + gid];
                uint32_t vb1 = Vs[ks * 8 + 4 + t4][nt * 8 + gid];
                mma_tf32(acc[nt], pa, vb0, vb1);
            }
        }
    }

    // Finalize: /rowsum, tf32-round, store O in PERMUTED column layout.
    // logical in-group cols are 2t4 and 2t4+1 -> phys p0, p1:
    const int p0 = (t4 < 2) ? 4 * t4     : 4 * t4 - 7;
    const int p1 = (t4 < 2) ? 4 * t4 + 2 : 4 * t4 - 5;
    float inv0 = 1.f / lrow0, inv1 = 1.f / lrow1;
    int r0 = qt * 64 + wrow + gid;
#pragma unroll
    for (int nt = 0; nt < 8; nt++) {
        int cg = nt * 8;
        O[base + (size_t)r0 * Dm + cg + p0]       = f2tff(acc[nt][0] * inv0);
        O[base + (size_t)r0 * Dm + cg + p1]       = f2tff(acc[nt][1] * inv0);
        O[base + (size_t)(r0 + 8) * Dm + cg + p0] = f2tff(acc[nt][2] * inv1);
        O[base + (size_t)(r0 + 8) * Dm + cg + p1] = f2tff(acc[nt][3] * inv1);
    }
}

// ============================================================================
// Launch
// ============================================================================
extern "C" void kernel_launch(void* const* d_in, const int* in_sizes, int n_in,
                              void* d_out, int out_size) {
    const float* x  = (const float*)d_in[0];
    const float* Wq = (const float*)d_in[1];
    const float* Wk = (const float*)d_in[2];
    const float* Wv = (const float*)d_in[3];
    const float* Wo = (const float*)d_in[4];
    const float* bq = (const float*)d_in[5];
    const float* bk = (const float*)d_in[6];
    const float* bv = (const float*)d_in[7];
    const float* bo = (const float*)d_in[8];
    float* out = (float*)d_out;

    float *gq, *gk, *gv, *go, *gxc, *gwc;
    cudaGetSymbolAddress((void**)&gq, g_Q);
    cudaGetSymbolAddress((void**)&gk, g_K);
    cudaGetSymbolAddress((void**)&gv, g_V);
    cudaGetSymbolAddress((void**)&go, g_O);
    cudaGetSymbolAddress((void**)&gxc, g_Xc);
    cudaGetSymbolAddress((void**)&gwc, g_Wc);
    const size_t WSZ = (size_t)NSP * Dm * Dm;

    cudaFuncSetAttribute(attn_kernel, cudaFuncAttributeMaxDynamicSharedMemorySize,
                         ATTN_SMEM);
    cudaFuncSetAttribute(gemm_qkv, cudaFuncAttributeMaxDynamicSharedMemorySize,
                         GEMM_SMEM_B);
    cudaFuncSetAttribute(gemm_o, cudaFuncAttributeMaxDynamicSharedMemorySize,
                         GEMM_SMEM_B);

    // Prep: x (round + permute), W x4 (round) — two launches
    const size_t XG = (size_t)NZ * Lb * Dm / 8;     // 8-float groups
    convert_x_perm<<<(unsigned)(XG / 256), 256>>>(x, gxc);
    convert_w<<<dim3((unsigned)(WSZ / 4 / 256), 1, 4), 256>>>(Wq, Wk, Wv, Wo, gwc);

    // Fused Q/K/V projections
    gemm_qkv<<<dim3(Dm / 128, Lb / 128, NZ * 3), 128, GEMM_SMEM_B>>>(
        gxc, gwc, bq, bk, bv, gq, gk, gv);

    attn_kernel<<<dim3(Lb / 64, NH, NZ), 128, ATTN_SMEM>>>(gq, gk, gv, go);

    gemm_o<<<dim3(Dm / 128, Lb / 128, NZ), 128, GEMM_SMEM_B>>>(
        go, gwc + 3 * WSZ, bo, out);
}

// round 9
// speedup vs baseline: 1.3635x; 1.0400x over previous
#include <cuda_runtime.h>
#include <cstdint>
#include <cmath>

// Problem constants
constexpr int Dm   = 1024;   // d_model
constexpr int Lb   = 1024;   // block length (SEQ / SPLIT)
constexpr int NSP  = 4;      // SPLIT
constexpr int NB   = 4;      // batch
constexpr int NH   = 16;     // heads
constexpr int DK   = 64;     // head dim
constexpr int NZ   = NB * NSP;  // 16 independent (b,s) blocks

// Scratch (allocation-free rule: __device__ globals)
__device__ float g_Q[(size_t)NZ * Lb * Dm];
__device__ float g_K[(size_t)NZ * Lb * Dm];
__device__ float g_V[(size_t)NZ * Lb * Dm];
__device__ float g_O[(size_t)NZ * Lb * Dm];      // k-interleave permuted layout
__device__ float g_Xc[(size_t)NZ * Lb * Dm];     // tf32-rounded, k-interleave permuted
__device__ float g_Wc[(size_t)4 * NSP * Dm * Dm];// tf32-rounded weights (plain layout)

// k-interleave permutation within each 8-column group:
//   logical l (0..7) -> phys p = (l<4) ? 2l : 2(l-4)+1

__device__ __forceinline__ uint32_t f2tf(float f) {
    uint32_t u;
    asm("cvt.rna.tf32.f32 %0, %1;" : "=r"(u) : "f"(f));
    return u;
}
__device__ __forceinline__ float f2tff(float f) {
    return __uint_as_float(f2tf(f));
}

__device__ __forceinline__ uint32_t smem_u32(const void* p) {
    uint32_t a;
    asm("{ .reg .u64 t; cvta.to.shared.u64 t, %1; cvt.u32.u64 %0, t; }"
        : "=r"(a) : "l"(p));
    return a;
}

__device__ __forceinline__ void cp16(uint32_t dst, const void* src) {
    asm volatile("cp.async.cg.shared.global [%0], [%1], 16;"
                 :: "r"(dst), "l"(src) : "memory");
}
#define CP_COMMIT() asm volatile("cp.async.commit_group;" ::: "memory")
#define CP_WAIT1()  asm volatile("cp.async.wait_group 1;" ::: "memory")

__device__ __forceinline__ void mma_tf32(float c[4], const uint32_t a[4],
                                         uint32_t b0, uint32_t b1) {
    asm volatile(
        "mma.sync.aligned.m16n8k8.row.col.f32.tf32.tf32.f32 "
        "{%0,%1,%2,%3}, {%4,%5,%6,%7}, {%8,%9}, {%0,%1,%2,%3};\n"
        : "+f"(c[0]), "+f"(c[1]), "+f"(c[2]), "+f"(c[3])
        : "r"(a[0]), "r"(a[1]), "r"(a[2]), "r"(a[3]), "r"(b0), "r"(b1));
}

// ============================================================================
// Converts (one-time prep)
// ============================================================================
__global__ __launch_bounds__(256) void convert_x_perm(const float* __restrict__ src,
                                                      float* __restrict__ dst) {
    size_t g = (size_t)blockIdx.x * 256 + threadIdx.x;   // 8-float group index
    const float4* s = (const float4*)src + g * 2;
    float4 a = s[0], b = s[1];                            // logical 0..3, 4..7
    float4 lo = make_float4(f2tff(a.x), f2tff(b.x), f2tff(a.y), f2tff(b.y));
    float4 hi = make_float4(f2tff(a.z), f2tff(b.z), f2tff(a.w), f2tff(b.w));
    ((float4*)dst)[g * 2]     = lo;
    ((float4*)dst)[g * 2 + 1] = hi;
}

__global__ __launch_bounds__(256) void convert_w(const float* __restrict__ w0,
                                                 const float* __restrict__ w1,
                                                 const float* __restrict__ w2,
                                                 const float* __restrict__ w3,
                                                 float* __restrict__ dst) {
    const int p = blockIdx.z;
    const float* src = (p == 0) ? w0 : (p == 1) ? w1 : (p == 2) ? w2 : w3;
    float* d = dst + (size_t)p * NSP * Dm * Dm;
    size_t i = (size_t)blockIdx.x * 256 + threadIdx.x;
    float4 v = ((const float4*)src)[i];
    v.x = f2tff(v.x); v.y = f2tff(v.y); v.z = f2tff(v.z); v.w = f2tff(v.w);
    ((float4*)d)[i] = v;
}

// ============================================================================
// GEMM core (unchanged from round 8): 128 threads, 4 warps x 64x64 tile,
// cp.async 3-stage, k-interleaved A (LDS.64 frags), conflict-free B.
// ============================================================================
constexpr int A_STR   = 40;
constexpr int B_STR   = 132;
constexpr int STAGE_AW = 128 * A_STR;
constexpr int STAGE_BW = 32 * B_STR;
constexpr int STAGE_W  = STAGE_AW + STAGE_BW;
constexpr int NSTAGE   = 3;
constexpr int GEMM_SMEM_B = NSTAGE * STAGE_W * 4;

template <bool TF32OUT>
__device__ __forceinline__ void gemm_core(const float* __restrict__ Xz,
                                          const float* __restrict__ Wz,
                                          const float* __restrict__ bz,
                                          float* __restrict__ Cz,
                                          uint32_t* smw) {
    const uint32_t sb = smem_u32(smw);
    const int m0 = blockIdx.y * 128, n0 = blockIdx.x * 128;
    const float* Xb = Xz + (size_t)m0 * Dm;
    const float* Wb = Wz + n0;
    const float* bb = bz + n0;
    float* Cb = Cz + (size_t)m0 * Dm + n0;

    const int tid = threadIdx.x;
    const int wid = tid >> 5, lane = tid & 31;
    const int gid = lane >> 2, t4 = lane & 3;
    const int wm = (wid & 1) * 64, wn = (wid >> 1) * 64;

    const int arow = tid >> 3, ac4 = tid & 7;
    const int bkr  = tid >> 5, bc4 = tid & 31;

    auto stage = [&](int c) {
        uint32_t base = sb + (uint32_t)(c % NSTAGE) * (STAGE_W * 4);
        const float* xa = Xb + c * 32;
        const float* wa = Wb + (size_t)c * 32 * Dm;
#pragma unroll
        for (int i = 0; i < 8; i++) {
            int r = arow + i * 16;
            cp16(base + (uint32_t)(r * A_STR + ac4 * 4) * 4,
                 xa + (size_t)r * Dm + ac4 * 4);
        }
#pragma unroll
        for (int i = 0; i < 8; i++) {
            int kr = bkr + i * 4;
            int l = kr & 7;
            int kp = (kr & ~7) | ((l < 4) ? 2 * l : 2 * (l - 4) + 1);
            cp16(base + (uint32_t)(STAGE_AW + kp * B_STR + bc4 * 4) * 4,
                 wa + (size_t)kr * Dm + bc4 * 4);
        }
    };

    float acc[4][8][4];
#pragma unroll
    for (int i = 0; i < 4; i++)
#pragma unroll
        for (int j = 0; j < 8; j++)
#pragma unroll
            for (int k = 0; k < 4; k++) acc[i][j][k] = 0.f;

    stage(0); CP_COMMIT();
    stage(1); CP_COMMIT();

    const int NCHUNK = Dm / 32;
    for (int c = 0; c < NCHUNK; c++) {
        CP_WAIT1();
        __syncthreads();
        if (c + 2 < NCHUNK) stage(c + 2);
        CP_COMMIT();

        const uint32_t* SA = smw + (c % NSTAGE) * STAGE_W;
        const uint32_t* SB = SA + STAGE_AW;
#pragma unroll
        for (int kk = 0; kk < 32; kk += 8) {
            uint32_t af[4][4], bf[8][2];
#pragma unroll
            for (int mt = 0; mt < 4; mt++) {
                int r0 = (wm + mt * 16 + gid) * A_STR;
                uint2 u0 = *(const uint2*)&SA[r0 + kk + 2 * t4];
                uint2 u1 = *(const uint2*)&SA[r0 + 8 * A_STR + kk + 2 * t4];
                af[mt][0] = u0.x; af[mt][1] = u1.x;
                af[mt][2] = u0.y; af[mt][3] = u1.y;
            }
#pragma unroll
            for (int nt = 0; nt < 8; nt++) {
                int cb = wn + nt * 8 + gid;
                bf[nt][0] = SB[(kk + 2 * t4) * B_STR + cb];
                bf[nt][1] = SB[(kk + 2 * t4 + 1) * B_STR + cb];
            }
#pragma unroll
            for (int mt = 0; mt < 4; mt++)
#pragma unroll
                for (int nt = 0; nt < 8; nt++)
                    mma_tf32(acc[mt][nt], af[mt], bf[nt][0], bf[nt][1]);
        }
    }

#pragma unroll
    for (int mt = 0; mt < 4; mt++) {
        int r0 = wm + mt * 16 + gid;
#pragma unroll
        for (int nt = 0; nt < 8; nt++) {
            int c0 = wn + nt * 8 + 2 * t4;
            float bv0 = bb[c0], bv1 = bb[c0 + 1];
            float v0 = acc[mt][nt][0] + bv0, v1 = acc[mt][nt][1] + bv1;
            float v2 = acc[mt][nt][2] + bv0, v3 = acc[mt][nt][3] + bv1;
            if (TF32OUT) {
                v0 = f2tff(v0); v1 = f2tff(v1); v2 = f2tff(v2); v3 = f2tff(v3);
            }
            *(float2*)(Cb + (size_t)r0 * Dm + c0)       = make_float2(v0, v1);
            *(float2*)(Cb + (size_t)(r0 + 8) * Dm + c0) = make_float2(v2, v3);
        }
    }
}

__global__ __launch_bounds__(128) void gemm_qkv(const float* __restrict__ X,
                                                const float* __restrict__ Wc,
                                                const float* __restrict__ bq,
                                                const float* __restrict__ bk,
                                                const float* __restrict__ bv,
                                                float* __restrict__ Qo,
                                                float* __restrict__ Ko,
                                                float* __restrict__ Vo) {
    extern __shared__ uint32_t smw[];
    const int proj = blockIdx.z / NZ;
    const int z    = blockIdx.z % NZ;
    const size_t WSZ = (size_t)NSP * Dm * Dm;
    const float* Xz = X + (size_t)z * Lb * Dm;
    const float* Wz = Wc + proj * WSZ + (size_t)(z % NSP) * Dm * Dm;
    const float* bz = ((proj == 0) ? bq : (proj == 1) ? bk : bv)
                      + (size_t)(z % NSP) * Dm;
    float* Cz = ((proj == 0) ? Qo : (proj == 1) ? Ko : Vo) + (size_t)z * Lb * Dm;
    gemm_core<true>(Xz, Wz, bz, Cz, smw);
}

__global__ __launch_bounds__(128) void gemm_o(const float* __restrict__ X,
                                              const float* __restrict__ Wz4,
                                              const float* __restrict__ bo,
                                              float* __restrict__ out) {
    extern __shared__ uint32_t smw[];
    const int z = blockIdx.z;
    gemm_core<false>(X + (size_t)z * Lb * Dm,
                     Wz4 + (size_t)(z % NSP) * Dm * Dm,
                     bo + (size_t)(z % NSP) * Dm,
                     out + (size_t)z * Lb * Dm, smw);
}

// ============================================================================
// Flash attention v2: 256 threads (8 warps x 16 rows = 128-row q-tile),
// cp.async DOUBLE-BUFFERED 64-key K/V tiles. Per-row math identical to v1
// (same 64-key tile order, same masks) -> bit-identical output.
// O written in k-interleave permuted layout for gemm_o.
// ============================================================================
constexpr int KS_STR = 68;
constexpr int VS_STR = 72;
constexpr int KV_STAGE_W = 64 * KS_STR + 64 * VS_STR;     // 8960 words / stage
constexpr int PS_OFF_W   = 2 * KV_STAGE_W;                // 17920
constexpr int ATTN_SMEM  = (PS_OFF_W + 128 * KS_STR) * 4; // 106496 B

__global__ __launch_bounds__(256, 2) void attn_kernel(const float* __restrict__ Q,
                                                      const float* __restrict__ K,
                                                      const float* __restrict__ V,
                                                      float* __restrict__ O) {
    extern __shared__ uint32_t sm[];
    const uint32_t sb = smem_u32(sm);
    uint32_t (*Ps)[KS_STR] = (uint32_t(*)[KS_STR])(sm + PS_OFF_W);

    const int qt = blockIdx.x;      // 128-row q tile (0..7)
    const int h  = blockIdx.y;
    const int z  = blockIdx.z;
    const size_t base = (size_t)z * Lb * Dm + h * DK;

    const int tid = threadIdx.x;
    const int wid = tid >> 5, lane = tid & 31;
    const int gid = lane >> 2, t4 = lane & 3;
    const int wrow = wid * 16;                    // 0..112
    const int jlast = 2 * qt + (wid >= 4 ? 1 : 0);
    const int jend  = 2 * qt + 1;
    const float scale = 0.125f;    // exact pow2: stays tf32-exact

    // Stage Q tile (scaled) into Ps: 128 rows x 64 cols
#pragma unroll
    for (int i = 0; i < 8; i++) {
        int r = i * 16 + (tid >> 4);
        int c = (tid & 15) * 4;
        float4 v = *(const float4*)(Q + base + (size_t)(qt * 128 + r) * Dm + c);
        v.x *= scale; v.y *= scale; v.z *= scale; v.w *= scale;
        *(float4*)&Ps[r][c] = v;
    }

    // K/V staging via cp.async: tile j -> buffer j&1
    auto stageKV = [&](int j) {
        uint32_t kbase = sb + (uint32_t)((j & 1) * KV_STAGE_W) * 4;
        uint32_t vbase = kbase + (uint32_t)(64 * KS_STR) * 4;
        const float* kp = K + base + (size_t)(j * 64) * Dm;
        const float* vp = V + base + (size_t)(j * 64) * Dm;
#pragma unroll
        for (int i = 0; i < 4; i++) {
            int r = i * 16 + (tid >> 4);
            int c = (tid & 15) * 4;
            cp16(kbase + (uint32_t)(r * KS_STR + c) * 4, kp + (size_t)r * Dm + c);
            cp16(vbase + (uint32_t)(r * VS_STR + c) * 4, vp + (size_t)r * Dm + c);
        }
    };

    stageKV(0); CP_COMMIT();
    stageKV(1); CP_COMMIT();

    __syncthreads();   // Ps (Q) visible to all warps

    uint32_t qa[8][4];
#pragma unroll
    for (int ks = 0; ks < 8; ks++) {
        qa[ks][0] = Ps[wrow + gid][ks * 8 + t4];
        qa[ks][1] = Ps[wrow + 8 + gid][ks * 8 + t4];
        qa[ks][2] = Ps[wrow + gid][ks * 8 + t4 + 4];
        qa[ks][3] = Ps[wrow + 8 + gid][ks * 8 + t4 + 4];
    }

    float acc[8][4];
#pragma unroll
    for (int nt = 0; nt < 8; nt++)
#pragma unroll
        for (int k = 0; k < 4; k++) acc[nt][k] = 0.f;
    float mrow0 = -INFINITY, mrow1 = -INFINITY;
    float lrow0 = 0.f, lrow1 = 0.f;

    for (int j = 0; j <= jend; j++) {
        CP_WAIT1();          // tile j's cp.async data landed
        __syncthreads();

        const uint32_t (*Ks)[KS_STR] =
            (const uint32_t(*)[KS_STR])(sm + (j & 1) * KV_STAGE_W);
        const uint32_t (*Vs)[VS_STR] =
            (const uint32_t(*)[VS_STR])(sm + (j & 1) * KV_STAGE_W + 64 * KS_STR);

        if (j <= jlast) {
            // S = (Q*scale) @ K^T
            float s[8][4];
#pragma unroll
            for (int nt = 0; nt < 8; nt++)
#pragma unroll
                for (int k = 0; k < 4; k++) s[nt][k] = 0.f;
#pragma unroll
            for (int ks = 0; ks < 8; ks++) {
#pragma unroll
                for (int nt = 0; nt < 8; nt++) {
                    uint32_t b0 = Ks[nt * 8 + gid][ks * 8 + t4];
                    uint32_t b1 = Ks[nt * 8 + gid][ks * 8 + t4 + 4];
                    mma_tf32(s[nt], qa[ks], b0, b1);
                }
            }

            // Causal mask (last tile this warp processes)
            if (j == jlast) {
                int koff = (j - 2 * qt) * 64;                // 0 or 64
                int r0 = wrow + gid, r1 = wrow + gid + 8;
#pragma unroll
                for (int nt = 0; nt < 8; nt++) {
                    int c0 = koff + nt * 8 + 2 * t4;
                    if (c0 > r0)     s[nt][0] = -1e30f;
                    if (c0 + 1 > r0) s[nt][1] = -1e30f;
                    if (c0 > r1)     s[nt][2] = -1e30f;
                    if (c0 + 1 > r1) s[nt][3] = -1e30f;
                }
            }

            // Online softmax
            float mx0 = -INFINITY, mx1 = -INFINITY;
#pragma unroll
            for (int nt = 0; nt < 8; nt++) {
                mx0 = fmaxf(mx0, fmaxf(s[nt][0], s[nt][1]));
                mx1 = fmaxf(mx1, fmaxf(s[nt][2], s[nt][3]));
            }
            mx0 = fmaxf(mx0, __shfl_xor_sync(0xffffffffu, mx0, 1));
            mx0 = fmaxf(mx0, __shfl_xor_sync(0xffffffffu, mx0, 2));
            mx1 = fmaxf(mx1, __shfl_xor_sync(0xffffffffu, mx1, 1));
            mx1 = fmaxf(mx1, __shfl_xor_sync(0xffffffffu, mx1, 2));

            float mn0 = fmaxf(mrow0, mx0), mn1 = fmaxf(mrow1, mx1);
            float cor0 = __expf(mrow0 - mn0), cor1 = __expf(mrow1 - mn1);
            mrow0 = mn0; mrow1 = mn1;

            float ls0 = 0.f, ls1 = 0.f;
#pragma unroll
            for (int nt = 0; nt < 8; nt++) {
                s[nt][0] = __expf(s[nt][0] - mn0);
                s[nt][1] = __expf(s[nt][1] - mn0);
                s[nt][2] = __expf(s[nt][2] - mn1);
                s[nt][3] = __expf(s[nt][3] - mn1);
                ls0 += s[nt][0] + s[nt][1];
                ls1 += s[nt][2] + s[nt][3];
            }
            ls0 += __shfl_xor_sync(0xffffffffu, ls0, 1);
            ls0 += __shfl_xor_sync(0xffffffffu, ls0, 2);
            ls1 += __shfl_xor_sync(0xffffffffu, ls1, 1);
            ls1 += __shfl_xor_sync(0xffffffffu, ls1, 2);
            lrow0 = lrow0 * cor0 + ls0;
            lrow1 = lrow1 * cor1 + ls1;

#pragma unroll
            for (int nt = 0; nt < 8; nt++) {
                acc[nt][0] *= cor0; acc[nt][1] *= cor0;
                acc[nt][2] *= cor1; acc[nt][3] *= cor1;
            }

            // Stage P (tf32) into warp-private Ps rows
#pragma unroll
            for (int nt = 0; nt < 8; nt++) {
                int c0 = nt * 8 + 2 * t4;
                Ps[wrow + gid][c0]         = f2tf(s[nt][0]);
                Ps[wrow + gid][c0 + 1]     = f2tf(s[nt][1]);
                Ps[wrow + 8 + gid][c0]     = f2tf(s[nt][2]);
                Ps[wrow + 8 + gid][c0 + 1] = f2tf(s[nt][3]);
            }
            __syncwarp();

            // O += P @ V
#pragma unroll
            for (int ks = 0; ks < 8; ks++) {
                uint32_t pa[4];
                pa[0] = Ps[wrow + gid][ks * 8 + t4];
                pa[1] = Ps[wrow + 8 + gid][ks * 8 + t4];
                pa[2] = Ps[wrow + gid][ks * 8 + t4 + 4];
                pa[3] = Ps[wrow + 8 + gid][ks * 8 + t4 + 4];
#pragma unroll
                for (int nt = 0; nt < 8; nt++) {
                    uint32_t vb0 = Vs[ks * 8 + t4][nt * 8 + gid];
                    uint32_t vb1 = Vs[ks * 8 + 4 + t4][nt * 8 + gid];
                    mma_tf32(acc[nt], pa, vb0, vb1);
                }
            }
        }

        __syncthreads();   // all warps done with buffer (j&1) before restage
        if (j + 2 <= jend) stageKV(j + 2);
        CP_COMMIT();
    }

    // Finalize: /rowsum, tf32-round, store O in PERMUTED column layout
    const int p0 = (t4 < 2) ? 4 * t4     : 4 * t4 - 7;
    const int p1 = (t4 < 2) ? 4 * t4 + 2 : 4 * t4 - 5;
    float inv0 = 1.f / lrow0, inv1 = 1.f / lrow1;
    int r0 = qt * 128 + wrow + gid;
#pragma unroll
    for (int nt = 0; nt < 8; nt++) {
        int cg = nt * 8;
        O[base + (size_t)r0 * Dm + cg + p0]       = f2tff(acc[nt][0] * inv0);
        O[base + (size_t)r0 * Dm + cg + p1]       = f2tff(acc[nt][1] * inv0);
        O[base + (size_t)(r0 + 8) * Dm + cg + p0] = f2tff(acc[nt][2] * inv1);
        O[base + (size_t)(r0 + 8) * Dm + cg + p1] = f2tff(acc[nt][3] * inv1);
    }
}

// ============================================================================
// Launch
// ============================================================================
extern "C" void kernel_launch(void* const* d_in, const int* in_sizes, int n_in,
                              void* d_out, int out_size) {
    const float* x  = (const float*)d_in[0];
    const float* Wq = (const float*)d_in[1];
    const float* Wk = (const float*)d_in[2];
    const float* Wv = (const float*)d_in[3];
    const float* Wo = (const float*)d_in[4];
    const float* bq = (const float*)d_in[5];
    const float* bk = (const float*)d_in[6];
    const float* bv = (const float*)d_in[7];
    const float* bo = (const float*)d_in[8];
    float* out = (float*)d_out;

    float *gq, *gk, *gv, *go, *gxc, *gwc;
    cudaGetSymbolAddress((void**)&gq, g_Q);
    cudaGetSymbolAddress((void**)&gk, g_K);
    cudaGetSymbolAddress((void**)&gv, g_V);
    cudaGetSymbolAddress((void**)&go, g_O);
    cudaGetSymbolAddress((void**)&gxc, g_Xc);
    cudaGetSymbolAddress((void**)&gwc, g_Wc);
    const size_t WSZ = (size_t)NSP * Dm * Dm;

    cudaFuncSetAttribute(attn_kernel, cudaFuncAttributeMaxDynamicSharedMemorySize,
                         ATTN_SMEM);
    cudaFuncSetAttribute(gemm_qkv, cudaFuncAttributeMaxDynamicSharedMemorySize,
                         GEMM_SMEM_B);
    cudaFuncSetAttribute(gemm_o, cudaFuncAttributeMaxDynamicSharedMemorySize,
                         GEMM_SMEM_B);

    const size_t XG = (size_t)NZ * Lb * Dm / 8;
    convert_x_perm<<<(unsigned)(XG / 256), 256>>>(x, gxc);
    convert_w<<<dim3((unsigned)(WSZ / 4 / 256), 1, 4), 256>>>(Wq, Wk, Wv, Wo, gwc);

    gemm_qkv<<<dim3(Dm / 128, Lb / 128, NZ * 3), 128, GEMM_SMEM_B>>>(
        gxc, gwc, bq, bk, bv, gq, gk, gv);

    attn_kernel<<<dim3(Lb / 128, NH, NZ), 256, ATTN_SMEM>>>(gq, gk, gv, go);

    gemm_o<<<dim3(Dm / 128, Lb / 128, NZ), 128, GEMM_SMEM_B>>>(
        go, gwc + 3 * WSZ, bo, out);
}

// round 10
// speedup vs baseline: 1.4670x; 1.0760x over previous
#include <cuda_runtime.h>
#include <cstdint>
#include <cmath>

// Problem constants
constexpr int Dm   = 1024;   // d_model
constexpr int Lb   = 1024;   // block length (SEQ / SPLIT)
constexpr int NSP  = 4;      // SPLIT
constexpr int NB   = 4;      // batch
constexpr int NH   = 16;     // heads
constexpr int DK   = 64;     // head dim
constexpr int NZ   = NB * NSP;  // 16 independent (b,s) blocks

// Scratch (allocation-free rule: __device__ globals)
__device__ float g_Q[(size_t)NZ * Lb * Dm];
__device__ float g_K[(size_t)NZ * Lb * Dm];
__device__ float g_V[(size_t)NZ * Lb * Dm];
__device__ float g_O[(size_t)NZ * Lb * Dm];      // k-interleave permuted layout
__device__ float g_Xc[(size_t)NZ * Lb * Dm];     // tf32-rounded, k-interleave permuted
__device__ float g_Wt[(size_t)4 * NSP * Dm * Dm];// tf32 W^T [n][k], k-interleave permuted

// k-interleave permutation within each 8-column group:
//   logical l (0..7) -> phys p = (l<4) ? 2l : 2(l-4)+1

__device__ __forceinline__ uint32_t f2tf(float f) {
    uint32_t u;
    asm("cvt.rna.tf32.f32 %0, %1;" : "=r"(u) : "f"(f));
    return u;
}
__device__ __forceinline__ float f2tff(float f) {
    return __uint_as_float(f2tf(f));
}

__device__ __forceinline__ uint32_t smem_u32(const void* p) {
    uint32_t a;
    asm("{ .reg .u64 t; cvta.to.shared.u64 t, %1; cvt.u32.u64 %0, t; }"
        : "=r"(a) : "l"(p));
    return a;
}

__device__ __forceinline__ void cp16(uint32_t dst, const void* src) {
    asm volatile("cp.async.cg.shared.global [%0], [%1], 16;"
                 :: "r"(dst), "l"(src) : "memory");
}
#define CP_COMMIT() asm volatile("cp.async.commit_group;" ::: "memory")
#define CP_WAIT1()  asm volatile("cp.async.wait_group 1;" ::: "memory")

__device__ __forceinline__ void mma_tf32(float c[4], const uint32_t a[4],
                                         uint32_t b0, uint32_t b1) {
    asm volatile(
        "mma.sync.aligned.m16n8k8.row.col.f32.tf32.tf32.f32 "
        "{%0,%1,%2,%3}, {%4,%5,%6,%7}, {%8,%9}, {%0,%1,%2,%3};\n"
        : "+f"(c[0]), "+f"(c[1]), "+f"(c[2]), "+f"(c[3])
        : "r"(a[0]), "r"(a[1]), "r"(a[2]), "r"(a[3]), "r"(b0), "r"(b1));
}

// ============================================================================
// Converts (one-time prep)
// ============================================================================
// x: tf32-round AND k-interleave permute each 8-col group.
__global__ __launch_bounds__(256) void convert_x_perm(const float* __restrict__ src,
                                                      float* __restrict__ dst) {
    size_t g = (size_t)blockIdx.x * 256 + threadIdx.x;   // 8-float group index
    const float4* s = (const float4*)src + g * 2;
    float4 a = s[0], b = s[1];                            // logical 0..3, 4..7
    float4 lo = make_float4(f2tff(a.x), f2tff(b.x), f2tff(a.y), f2tff(b.y));
    float4 hi = make_float4(f2tff(a.z), f2tff(b.z), f2tff(a.w), f2tff(b.w));
    ((float4*)dst)[g * 2]     = lo;
    ((float4*)dst)[g * 2 + 1] = hi;
}

// W: transpose (W^T[n][k] = W[k][n]), tf32-round, and k-interleave permute
// the k (contiguous) dimension. grid.z = proj*NSP+split (16 matrices).
__global__ __launch_bounds__(256) void convert_w_t(const float* __restrict__ w0,
                                                   const float* __restrict__ w1,
                                                   const float* __restrict__ w2,
                                                   const float* __restrict__ w3,
                                                   float* __restrict__ dst) {
    __shared__ float t[32][33];
    const int zz = blockIdx.z;           // 0..15
    const int p = zz >> 2, s = zz & 3;
    const float* src = (p == 0) ? w0 : (p == 1) ? w1 : (p == 2) ? w2 : w3;
    const float* Wb = src + (size_t)s * Dm * Dm;
    float* Tb = dst + ((size_t)p * NSP + s) * Dm * Dm;

    const int k0 = blockIdx.y * 32, n0 = blockIdx.x * 32;
    const int x = threadIdx.x & 31, y = (threadIdx.x >> 5) ;   // 32 x 8
#pragma unroll
    for (int i = 0; i < 32; i += 8)
        t[y + i][x] = f2tff(Wb[(size_t)(k0 + y + i) * Dm + n0 + x]);
    __syncthreads();
    // k index = k0 + x -> permuted within its 8-group
    const int xl = x & 7;
    const int kp = (x & 24) | ((xl < 4) ? 2 * xl : 2 * (xl - 4) + 1);
#pragma unroll
    for (int i = 0; i < 32; i += 8)
        Tb[(size_t)(n0 + y + i) * Dm + k0 + kp] = t[x][y + i];
}

// ============================================================================
// GEMM core: 128 threads, 4 warps x 64x64 tile, cp.async 3-stage.
// BOTH operands are [128 rows][32 k-words] tiles, XOR-swizzled
// (word w at row r -> w ^ ((r&3)<<3)): conflict-free cp16 writes and
// LDS.64 fragment reads for A and B. k-interleave handled in global layout.
// ============================================================================
constexpr int TILE_W  = 128 * 32;            // words per operand tile
constexpr int STAGE_W = 2 * TILE_W;          // 8192 words = 32768 B
constexpr int NSTAGE  = 3;
constexpr int GEMM_SMEM_B = NSTAGE * STAGE_W * 4;   // 98304 B -> 2 CTAs/SM

template <bool TF32OUT>
__device__ __forceinline__ void gemm_core(const float* __restrict__ Xz,
                                          const float* __restrict__ Wtz,
                                          const float* __restrict__ bz,
                                          float* __restrict__ Cz,
                                          uint32_t* smw) {
    const uint32_t sb = smem_u32(smw);
    const int m0 = blockIdx.y * 128, n0 = blockIdx.x * 128;
    const float* Xb = Xz + (size_t)m0 * Dm;
    const float* Wb = Wtz + (size_t)n0 * Dm;    // W^T rows are n
    const float* bb = bz + n0;
    float* Cb = Cz + (size_t)m0 * Dm + n0;

    const int tid = threadIdx.x;
    const int wid = tid >> 5, lane = tid & 31;
    const int gid = lane >> 2, t4 = lane & 3;
    const int wm = (wid & 1) * 64, wn = (wid >> 1) * 64;

    const int arow = tid >> 3, ac4 = tid & 7;
    const uint32_t sww = (uint32_t)((ac4 * 4) ^ ((arow & 3) << 3));  // (r&3) invariant: r=arow+16i

    auto stage = [&](int c) {
        uint32_t base = sb + (uint32_t)(c % NSTAGE) * (STAGE_W * 4);
        const float* xa = Xb + c * 32;
        const float* wa = Wb + c * 32;
#pragma unroll
        for (int i = 0; i < 8; i++) {
            int r = arow + i * 16;
            cp16(base + (uint32_t)(r * 32) * 4 + sww * 4, xa + (size_t)r * Dm + ac4 * 4);
            cp16(base + (uint32_t)(TILE_W + r * 32) * 4 + sww * 4, wa + (size_t)r * Dm + ac4 * 4);
        }
    };

    float acc[4][8][4];
#pragma unroll
    for (int i = 0; i < 4; i++)
#pragma unroll
        for (int j = 0; j < 8; j++)
#pragma unroll
            for (int k = 0; k < 4; k++) acc[i][j][k] = 0.f;

    stage(0); CP_COMMIT();
    stage(1); CP_COMMIT();

    const int fsw = (gid & 3) << 3;          // frag-read XOR term
    const int NCHUNK = Dm / 32;
    for (int c = 0; c < NCHUNK; c++) {
        CP_WAIT1();
        __syncthreads();
        if (c + 2 < NCHUNK) stage(c + 2);
        CP_COMMIT();

        const uint32_t* SA = smw + (c % NSTAGE) * STAGE_W;
        const uint32_t* SB = SA + TILE_W;
#pragma unroll
        for (int kk = 0; kk < 32; kk += 8) {
            const int wsw = (kk + 2 * t4) ^ fsw;
            uint32_t af[4][4], bf[8][2];
#pragma unroll
            for (int mt = 0; mt < 4; mt++) {
                int r0 = (wm + mt * 16 + gid) * 32;
                uint2 u0 = *(const uint2*)&SA[r0 + wsw];
                uint2 u1 = *(const uint2*)&SA[r0 + 8 * 32 + wsw];
                af[mt][0] = u0.x; af[mt][1] = u1.x;
                af[mt][2] = u0.y; af[mt][3] = u1.y;
            }
#pragma unroll
            for (int nt = 0; nt < 8; nt++) {
                int rb = (wn + nt * 8 + gid) * 32;
                uint2 ub = *(const uint2*)&SB[rb + wsw];
                bf[nt][0] = ub.x;     // logical k = t4
                bf[nt][1] = ub.y;     // logical k = t4+4
            }
#pragma unroll
            for (int mt = 0; mt < 4; mt++)
#pragma unroll
                for (int nt = 0; nt < 8; nt++)
                    mma_tf32(acc[mt][nt], af[mt], bf[nt][0], bf[nt][1]);
        }
    }

    // Epilogue: + bias (TF32OUT rounds for attention consumers); logical layout
#pragma unroll
    for (int mt = 0; mt < 4; mt++) {
        int r0 = wm + mt * 16 + gid;
#pragma unroll
        for (int nt = 0; nt < 8; nt++) {
            int c0 = wn + nt * 8 + 2 * t4;
            float bv0 = bb[c0], bv1 = bb[c0 + 1];
            float v0 = acc[mt][nt][0] + bv0, v1 = acc[mt][nt][1] + bv1;
            float v2 = acc[mt][nt][2] + bv0, v3 = acc[mt][nt][3] + bv1;
            if (TF32OUT) {
                v0 = f2tff(v0); v1 = f2tff(v1); v2 = f2tff(v2); v3 = f2tff(v3);
            }
            *(float2*)(Cb + (size_t)r0 * Dm + c0)       = make_float2(v0, v1);
            *(float2*)(Cb + (size_t)(r0 + 8) * Dm + c0) = make_float2(v2, v3);
        }
    }
}

__global__ __launch_bounds__(128) void gemm_qkv(const float* __restrict__ X,
                                                const float* __restrict__ Wt,
                                                const float* __restrict__ bq,
                                                const float* __restrict__ bk,
                                                const float* __restrict__ bv,
                                                float* __restrict__ Qo,
                                                float* __restrict__ Ko,
                                                float* __restrict__ Vo) {
    extern __shared__ uint32_t smw[];
    const int proj = blockIdx.z / NZ;
    const int z    = blockIdx.z % NZ;
    const size_t WSZ = (size_t)NSP * Dm * Dm;
    const float* Xz = X + (size_t)z * Lb * Dm;
    const float* Wz = Wt + proj * WSZ + (size_t)(z % NSP) * Dm * Dm;
    const float* bz = ((proj == 0) ? bq : (proj == 1) ? bk : bv)
                      + (size_t)(z % NSP) * Dm;
    float* Cz = ((proj == 0) ? Qo : (proj == 1) ? Ko : Vo) + (size_t)z * Lb * Dm;
    gemm_core<true>(Xz, Wz, bz, Cz, smw);
}

__global__ __launch_bounds__(128) void gemm_o(const float* __restrict__ X,
                                              const float* __restrict__ Wtz4,
                                              const float* __restrict__ bo,
                                              float* __restrict__ out) {
    extern __shared__ uint32_t smw[];
    const int z = blockIdx.z;
    gemm_core<false>(X + (size_t)z * Lb * Dm,
                     Wtz4 + (size_t)(z % NSP) * Dm * Dm,
                     bo + (size_t)(z % NSP) * Dm,
                     out + (size_t)z * Lb * Dm, smw);
}

// ============================================================================
// Flash attention (unchanged from round 9): 256 threads, 128-row q-tiles,
// cp.async double-buffered 64-key K/V tiles. O written permuted for gemm_o.
// ============================================================================
constexpr int KS_STR = 68;
constexpr int VS_STR = 72;
constexpr int KV_STAGE_W = 64 * KS_STR + 64 * VS_STR;
constexpr int PS_OFF_W   = 2 * KV_STAGE_W;
constexpr int ATTN_SMEM  = (PS_OFF_W + 128 * KS_STR) * 4;

__global__ __launch_bounds__(256, 2) void attn_kernel(const float* __restrict__ Q,
                                                      const float* __restrict__ K,
                                                      const float* __restrict__ V,
                                                      float* __restrict__ O) {
    extern __shared__ uint32_t sm[];
    const uint32_t sb = smem_u32(sm);
    uint32_t (*Ps)[KS_STR] = (uint32_t(*)[KS_STR])(sm + PS_OFF_W);

    const int qt = blockIdx.x;
    const int h  = blockIdx.y;
    const int z  = blockIdx.z;
    const size_t base = (size_t)z * Lb * Dm + h * DK;

    const int tid = threadIdx.x;
    const int wid = tid >> 5, lane = tid & 31;
    const int gid = lane >> 2, t4 = lane & 3;
    const int wrow = wid * 16;
    const int jlast = 2 * qt + (wid >= 4 ? 1 : 0);
    const int jend  = 2 * qt + 1;
    const float scale = 0.125f;

#pragma unroll
    for (int i = 0; i < 8; i++) {
        int r = i * 16 + (tid >> 4);
        int c = (tid & 15) * 4;
        float4 v = *(const float4*)(Q + base + (size_t)(qt * 128 + r) * Dm + c);
        v.x *= scale; v.y *= scale; v.z *= scale; v.w *= scale;
        *(float4*)&Ps[r][c] = v;
    }

    auto stageKV = [&](int j) {
        uint32_t kbase = sb + (uint32_t)((j & 1) * KV_STAGE_W) * 4;
        uint32_t vbase = kbase + (uint32_t)(64 * KS_STR) * 4;
        const float* kp = K + base + (size_t)(j * 64) * Dm;
        const float* vp = V + base + (size_t)(j * 64) * Dm;
#pragma unroll
        for (int i = 0; i < 4; i++) {
            int r = i * 16 + (tid >> 4);
            int c = (tid & 15) * 4;
            cp16(kbase + (uint32_t)(r * KS_STR + c) * 4, kp + (size_t)r * Dm + c);
            cp16(vbase + (uint32_t)(r * VS_STR + c) * 4, vp + (size_t)r * Dm + c);
        }
    };

    stageKV(0); CP_COMMIT();
    stageKV(1); CP_COMMIT();

    __syncthreads();

    uint32_t qa[8][4];
#pragma unroll
    for (int ks = 0; ks < 8; ks++) {
        qa[ks][0] = Ps[wrow + gid][ks * 8 + t4];
        qa[ks][1] = Ps[wrow + 8 + gid][ks * 8 + t4];
        qa[ks][2] = Ps[wrow + gid][ks * 8 + t4 + 4];
        qa[ks][3] = Ps[wrow + 8 + gid][ks * 8 + t4 + 4];
    }

    float acc[8][4];
#pragma unroll
    for (int nt = 0; nt < 8; nt++)
#pragma unroll
        for (int k = 0; k < 4; k++) acc[nt][k] = 0.f;
    float mrow0 = -INFINITY, mrow1 = -INFINITY;
    float lrow0 = 0.f, lrow1 = 0.f;

    for (int j = 0; j <= jend; j++) {
        CP_WAIT1();
        __syncthreads();

        const uint32_t (*Ks)[KS_STR] =
            (const uint32_t(*)[KS_STR])(sm + (j & 1) * KV_STAGE_W);
        const uint32_t (*Vs)[VS_STR] =
            (const uint32_t(*)[VS_STR])(sm + (j & 1) * KV_STAGE_W + 64 * KS_STR);

        if (j <= jlast) {
            float s[8][4];
#pragma unroll
            for (int nt = 0; nt < 8; nt++)
#pragma unroll
                for (int k = 0; k < 4; k++) s[nt][k] = 0.f;
#pragma unroll
            for (int ks = 0; ks < 8; ks++) {
#pragma unroll
                for (int nt = 0; nt < 8; nt++) {
                    uint32_t b0 = Ks[nt * 8 + gid][ks * 8 + t4];
                    uint32_t b1 = Ks[nt * 8 + gid][ks * 8 + t4 + 4];
                    mma_tf32(s[nt], qa[ks], b0, b1);
                }
            }

            if (j == jlast) {
                int koff = (j - 2 * qt) * 64;
                int r0 = wrow + gid, r1 = wrow + gid + 8;
#pragma unroll
                for (int nt = 0; nt < 8; nt++) {
                    int c0 = koff + nt * 8 + 2 * t4;
                    if (c0 > r0)     s[nt][0] = -1e30f;
                    if (c0 + 1 > r0) s[nt][1] = -1e30f;
                    if (c0 > r1)     s[nt][2] = -1e30f;
                    if (c0 + 1 > r1) s[nt][3] = -1e30f;
                }
            }

            float mx0 = -INFINITY, mx1 = -INFINITY;
#pragma unroll
            for (int nt = 0; nt < 8; nt++) {
                mx0 = fmaxf(mx0, fmaxf(s[nt][0], s[nt][1]));
                mx1 = fmaxf(mx1, fmaxf(s[nt][2], s[nt][3]));
            }
            mx0 = fmaxf(mx0, __shfl_xor_sync(0xffffffffu, mx0, 1));
            mx0 = fmaxf(mx0, __shfl_xor_sync(0xffffffffu, mx0, 2));
            mx1 = fmaxf(mx1, __shfl_xor_sync(0xffffffffu, mx1, 1));
            mx1 = fmaxf(mx1, __shfl_xor_sync(0xffffffffu, mx1, 2));

            float mn0 = fmaxf(mrow0, mx0), mn1 = fmaxf(mrow1, mx1);
            float cor0 = __expf(mrow0 - mn0), cor1 = __expf(mrow1 - mn1);
            mrow0 = mn0; mrow1 = mn1;

            float ls0 = 0.f, ls1 = 0.f;
#pragma unroll
            for (int nt = 0; nt < 8; nt++) {
                s[nt][0] = __expf(s[nt][0] - mn0);
                s[nt][1] = __expf(s[nt][1] - mn0);
                s[nt][2] = __expf(s[nt][2] - mn1);
                s[nt][3] = __expf(s[nt][3] - mn1);
                ls0 += s[nt][0] + s[nt][1];
                ls1 += s[nt][2] + s[nt][3];
            }
            ls0 += __shfl_xor_sync(0xffffffffu, ls0, 1);
            ls0 += __shfl_xor_sync(0xffffffffu, ls0, 2);
            ls1 += __shfl_xor_sync(0xffffffffu, ls1, 1);
            ls1 += __shfl_xor_sync(0xffffffffu, ls1, 2);
            lrow0 = lrow0 * cor0 + ls0;
            lrow1 = lrow1 * cor1 + ls1;

#pragma unroll
            for (int nt = 0; nt < 8; nt++) {
                acc[nt][0] *= cor0; acc[nt][1] *= cor0;
                acc[nt][2] *= cor1; acc[nt][3] *= cor1;
            }

#pragma unroll
            for (int nt = 0; nt < 8; nt++) {
                int c0 = nt * 8 + 2 * t4;
                Ps[wrow + gid][c0]         = f2tf(s[nt][0]);
                Ps[wrow + gid][c0 + 1]     = f2tf(s[nt][1]);
                Ps[wrow + 8 + gid][c0]     = f2tf(s[nt][2]);
                Ps[wrow + 8 + gid][c0 + 1] = f2tf(s[nt][3]);
            }
            __syncwarp();

#pragma unroll
            for (int ks = 0; ks < 8; ks++) {
                uint32_t pa[4];
                pa[0] = Ps[wrow + gid][ks * 8 + t4];
                pa[1] = Ps[wrow + 8 + gid][ks * 8 + t4];
                pa[2] = Ps[wrow + gid][ks * 8 + t4 + 4];
                pa[3] = Ps[wrow + 8 + gid][ks * 8 + t4 + 4];
#pragma unroll
                for (int nt = 0; nt < 8; nt++) {
                    uint32_t vb0 = Vs[ks * 8 + t4][nt * 8 + gid];
                    uint32_t vb1 = Vs[ks * 8 + 4 + t4][nt * 8 + gid];
                    mma_tf32(acc[nt], pa, vb0, vb1);
                }
            }
        }

        __syncthreads();
        if (j + 2 <= jend) stageKV(j + 2);
        CP_COMMIT();
    }

    const int p0 = (t4 < 2) ? 4 * t4     : 4 * t4 - 7;
    const int p1 = (t4 < 2) ? 4 * t4 + 2 : 4 * t4 - 5;
    float inv0 = 1.f / lrow0, inv1 = 1.f / lrow1;
    int r0 = qt * 128 + wrow + gid;
#pragma unroll
    for (int nt = 0; nt < 8; nt++) {
        int cg = nt * 8;
        O[base + (size_t)r0 * Dm + cg + p0]       = f2tff(acc[nt][0] * inv0);
        O[base + (size_t)r0 * Dm + cg + p1]       = f2tff(acc[nt][1] * inv0);
        O[base + (size_t)(r0 + 8) * Dm + cg + p0] = f2tff(acc[nt][2] * inv1);
        O[base + (size_t)(r0 + 8) * Dm + cg + p1] = f2tff(acc[nt][3] * inv1);
    }
}

// ============================================================================
// Launch
// ============================================================================
extern "C" void kernel_launch(void* const* d_in, const int* in_sizes, int n_in,
                              void* d_out, int out_size) {
    const float* x  = (const float*)d_in[0];
    const float* Wq = (const float*)d_in[1];
    const float* Wk = (const float*)d_in[2];
    const float* Wv = (const float*)d_in[3];
    const float* Wo = (const float*)d_in[4];
    const float* bq = (const float*)d_in[5];
    const float* bk = (const float*)d_in[6];
    const float* bv = (const float*)d_in[7];
    const float* bo = (const float*)d_in[8];
    float* out = (float*)d_out;

    float *gq, *gk, *gv, *go, *gxc, *gwt;
    cudaGetSymbolAddress((void**)&gq, g_Q);
    cudaGetSymbolAddress((void**)&gk, g_K);
    cudaGetSymbolAddress((void**)&gv, g_V);
    cudaGetSymbolAddress((void**)&go, g_O);
    cudaGetSymbolAddress((void**)&gxc, g_Xc);
    cudaGetSymbolAddress((void**)&gwt, g_Wt);
    const size_t WSZ = (size_t)NSP * Dm * Dm;

    cudaFuncSetAttribute(attn_kernel, cudaFuncAttributeMaxDynamicSharedMemorySize,
                         ATTN_SMEM);
    cudaFuncSetAttribute(gemm_qkv, cudaFuncAttributeMaxDynamicSharedMemorySize,
                         GEMM_SMEM_B);
    cudaFuncSetAttribute(gemm_o, cudaFuncAttributeMaxDynamicSharedMemorySize,
                         GEMM_SMEM_B);

    const size_t XG = (size_t)NZ * Lb * Dm / 8;
    convert_x_perm<<<(unsigned)(XG / 256), 256>>>(x, gxc);
    convert_w_t<<<dim3(32, 32, 16), 256>>>(Wq, Wk, Wv, Wo, gwt);

    gemm_qkv<<<dim3(Dm / 128, Lb / 128, NZ * 3), 128, GEMM_SMEM_B>>>(
        gxc, gwt, bq, bk, bv, gq, gk, gv);

    attn_kernel<<<dim3(Lb / 128, NH, NZ), 256, ATTN_SMEM>>>(gq, gk, gv, go);

    gemm_o<<<dim3(Dm / 128, Lb / 128, NZ), 128, GEMM_SMEM_B>>>(
        go, gwt + 3 * WSZ, bo, out);
}